// round 2
// baseline (speedup 1.0000x reference)
#include <cuda_runtime.h>
#include <math.h>

#define BB 8
#define CC 1024
#define QQ 128
#define EE 512
#define HH 1024
#define FE 2048  /* 4*E */

// ---------------- scratch (static device globals; no allocation) -------------
__device__ float g_qw[BB * QQ];
__device__ float g_cw[BB * CC];
__device__ float g_qmT[BB * EE * QQ];
__device__ float g_sim[BB * CC * QQ];          // reused as softmax probs P
__device__ float g_rowmax[BB * CC];
__device__ float g_cwsoft[BB * CC];
__device__ float g_q2c[BB * EE];
__device__ float g_c2q[BB * CC * EE];
__device__ float g_att[BB * CC * FE];
__device__ float g_h[BB * CC * HH];

// ---------------- small helpers ---------------------------------------------
__device__ __forceinline__ float warp_sum(float v) {
    #pragma unroll
    for (int o = 16; o > 0; o >>= 1) v += __shfl_xor_sync(0xFFFFFFFFu, v, o);
    return v;
}
__device__ __forceinline__ float warp_max(float v) {
    #pragma unroll
    for (int o = 16; o > 0; o >>= 1) v = fmaxf(v, __shfl_xor_sync(0xFFFFFFFFu, v, o));
    return v;
}

// out[row] = dot(X[row,:], w)  — warp per row, E multiple of 128
__global__ void rows_dot_kernel(const float* __restrict__ X,
                                const float* __restrict__ w,
                                float* __restrict__ out, int E) {
    int row  = blockIdx.x * 8 + (threadIdx.x >> 5);
    int lane = threadIdx.x & 31;
    const float4* x  = (const float4*)(X + (long)row * E);
    const float4* wv = (const float4*)w;
    float s = 0.f;
    for (int i = lane; i * 4 < E; i += 32) {
        float4 a = x[i], b = wv[i];
        s += a.x * b.x + a.y * b.y + a.z * b.z + a.w * b.w;
    }
    s = warp_sum(s);
    if (lane == 0) out[row] = s;
}

// qmT[b,e,q] = question[b,q,e] * w_mult[e]   (tiled transpose)
__global__ void make_qmT_kernel(const float* __restrict__ question,
                                const float* __restrict__ wm,
                                float* __restrict__ qmT) {
    __shared__ float t[32][33];
    int b  = blockIdx.z;
    int q0 = blockIdx.x * 32, e0 = blockIdx.y * 32;
    int tx = threadIdx.x, ty = threadIdx.y;   // 32 x 8
    #pragma unroll
    for (int i = 0; i < 4; i++)
        t[ty + i * 8][tx] =
            question[((long)b * QQ + q0 + ty + i * 8) * EE + e0 + tx] * wm[e0 + tx];
    __syncthreads();
    #pragma unroll
    for (int i = 0; i < 4; i++)
        qmT[((long)b * EE + e0 + ty + i * 8) * QQ + q0 + tx] = t[tx][ty + i * 8];
}

// ---------------- generic 128x128x16 tiled GEMM ------------------------------
// MODE 0: C = acc
// MODE 1: C = acc + aux1[z*a1s + row] + aux2[z*a2s + col]          (sim)
// MODE 2: C = (acc + aux1[col]) * aux2[row]                        (h)
// MODE 3: C = relu((acc + aux1[col]) * aux2[row])                  (out)
template <int MODE>
__global__ void __launch_bounds__(256) gemm128(
    const float* __restrict__ A, const float* __restrict__ B, float* __restrict__ C,
    int M, int N, int K, long sA, long sB, long sC,
    const float* __restrict__ aux1, int a1s,
    const float* __restrict__ aux2, int a2s) {
    __shared__ float As[16][128];
    __shared__ float Bs[16][128];
    int z = blockIdx.z;
    A += (long)z * sA; B += (long)z * sB; C += (long)z * sC;

    int tid = threadIdx.x;
    int tx = tid & 15, ty = tid >> 4;
    int rowBase = blockIdx.y * 128;
    int colBase = blockIdx.x * 128;

    int aRow = tid >> 2;            // 0..63
    int aCol = (tid & 3) << 2;      // 0,4,8,12
    int bRow = tid >> 5;            // 0..7
    int bCol = (tid & 31) << 2;     // 0..124

    float acc[8][8];
    #pragma unroll
    for (int i = 0; i < 8; i++)
        #pragma unroll
        for (int j = 0; j < 8; j++) acc[i][j] = 0.f;

    for (int k0 = 0; k0 < K; k0 += 16) {
        #pragma unroll
        for (int i = 0; i < 2; i++) {
            float4 v = *(const float4*)(A + (long)(rowBase + aRow + i * 64) * K + k0 + aCol);
            As[aCol + 0][aRow + i * 64] = v.x;
            As[aCol + 1][aRow + i * 64] = v.y;
            As[aCol + 2][aRow + i * 64] = v.z;
            As[aCol + 3][aRow + i * 64] = v.w;
        }
        #pragma unroll
        for (int i = 0; i < 2; i++) {
            float4 v = *(const float4*)(B + (long)(k0 + bRow + i * 8) * N + colBase + bCol);
            *(float4*)&Bs[bRow + i * 8][bCol] = v;
        }
        __syncthreads();
        #pragma unroll
        for (int kk = 0; kk < 16; kk++) {
            float a[8], bb[8];
            #pragma unroll
            for (int i = 0; i < 4; i++) {
                a[i]      = As[kk][ty * 4 + i];
                a[i + 4]  = As[kk][64 + ty * 4 + i];
                bb[i]     = Bs[kk][tx * 4 + i];
                bb[i + 4] = Bs[kk][64 + tx * 4 + i];
            }
            #pragma unroll
            for (int i = 0; i < 8; i++)
                #pragma unroll
                for (int j = 0; j < 8; j++) acc[i][j] += a[i] * bb[j];
        }
        __syncthreads();
    }

    #pragma unroll
    for (int i = 0; i < 8; i++) {
        int r = rowBase + ((i < 4) ? ty * 4 + i : 64 + ty * 4 + (i - 4));
        #pragma unroll
        for (int j = 0; j < 8; j++) {
            int c = colBase + ((j < 4) ? tx * 4 + j : 64 + tx * 4 + (j - 4));
            float v = acc[i][j];
            if (MODE == 1) v += aux1[z * a1s + r] + aux2[z * a2s + c];
            else if (MODE == 2) v = (v + aux1[c]) * aux2[r];
            else if (MODE == 3) v = fmaxf(0.f, (v + aux1[c]) * aux2[r]);
            C[(long)r * N + c] = v;
        }
    }
}

// ---------------- softmax over q (Q=128), warp per row; also rowmax ----------
__global__ void softmax_q_kernel(float* __restrict__ sim, float* __restrict__ rowmax) {
    int row  = blockIdx.x * 8 + (threadIdx.x >> 5);
    int lane = threadIdx.x & 31;
    float4* p = (float4*)(sim + (long)row * QQ);
    float4 v = p[lane];
    float m = fmaxf(fmaxf(v.x, v.y), fmaxf(v.z, v.w));
    m = warp_max(m);
    float ex = __expf(v.x - m), ey = __expf(v.y - m),
          ez = __expf(v.z - m), ew = __expf(v.w - m);
    float s = warp_sum(ex + ey + ez + ew);
    float inv = 1.f / s;
    p[lane] = make_float4(ex * inv, ey * inv, ez * inv, ew * inv);
    if (lane == 0) rowmax[row] = m;
}

// ---------------- softmax over c (C=1024) per batch --------------------------
__global__ void softmax_c_kernel(const float* __restrict__ rowmax,
                                 float* __restrict__ cwsoft) {
    int b   = blockIdx.x;
    int tid = threadIdx.x;
    int wid = tid >> 5, lane = tid & 31;
    __shared__ float redm[8], reds[8];
    float4 v = ((const float4*)(rowmax + b * CC))[tid];   // 256*4 = 1024
    float m = fmaxf(fmaxf(v.x, v.y), fmaxf(v.z, v.w));
    m = warp_max(m);
    if (lane == 0) redm[wid] = m;
    __syncthreads();
    float bm = redm[0];
    #pragma unroll
    for (int i = 1; i < 8; i++) bm = fmaxf(bm, redm[i]);
    float ex = __expf(v.x - bm), ey = __expf(v.y - bm),
          ez = __expf(v.z - bm), ew = __expf(v.w - bm);
    float s = warp_sum(ex + ey + ez + ew);
    if (lane == 0) reds[wid] = s;
    __syncthreads();
    float bs = 0.f;
    #pragma unroll
    for (int i = 0; i < 8; i++) bs += reds[i];
    float inv = 1.f / bs;
    ((float4*)(cwsoft + b * CC))[tid] =
        make_float4(ex * inv, ey * inv, ez * inv, ew * inv);
}

// ---------------- q2c[b,e] = sum_c cwsoft[b,c]*context[b,c,e] -----------------
__global__ void q2c_kernel(const float* __restrict__ context,
                           const float* __restrict__ cwsoft,
                           float* __restrict__ q2c) {
    int idx = blockIdx.x * 256 + threadIdx.x;   // B*E = 4096 threads
    int b = idx / EE, e = idx % EE;
    const float* ctx = context + (long)b * CC * EE + e;
    const float* w   = cwsoft + b * CC;
    float s = 0.f;
    #pragma unroll 4
    for (int c = 0; c < CC; c++) s += w[c] * ctx[(long)c * EE];
    q2c[idx] = s;
}

// ---------------- attended = [ctx, c2q, ctx*c2q, ctx*q2c] --------------------
__global__ void build_att_kernel(const float* __restrict__ ctx,
                                 const float* __restrict__ c2q,
                                 const float* __restrict__ q2c,
                                 float* __restrict__ att) {
    long idx = (long)blockIdx.x * 256 + threadIdx.x;
    int  k   = (int)(idx & (FE - 1));
    long bc  = idx >> 11;            // / 2048
    int  e   = k & (EE - 1);
    int  seg = k >> 9;
    int  b   = (int)(bc >> 10);      // / 1024
    float cv = ctx[bc * EE + e];
    float v;
    if (seg == 0)       v = cv;
    else if (seg == 3)  v = cv * q2c[b * EE + e];
    else {
        float t = c2q[bc * EE + e];
        v = (seg == 1) ? t : cv * t;
    }
    att[idx] = v;
}

// ---------------- launch -----------------------------------------------------
extern "C" void kernel_launch(void* const* d_in, const int* in_sizes, int n_in,
                              void* d_out, int out_size) {
    const float* context  = (const float*)d_in[0];
    const float* question = (const float*)d_in[1];
    const float* mask     = (const float*)d_in[2];
    const float* w_q      = (const float*)d_in[3];
    const float* w_c      = (const float*)d_in[4];
    const float* w_m      = (const float*)d_in[5];
    const float* W1       = (const float*)d_in[6];
    const float* b1       = (const float*)d_in[7];
    const float* W2       = (const float*)d_in[8];
    const float* b2       = (const float*)d_in[9];
    float* out = (float*)d_out;

    float *qw, *cw, *qmT, *sim, *rowmax, *cwsoft, *q2c, *c2q, *att, *h;
    cudaGetSymbolAddress((void**)&qw,     g_qw);
    cudaGetSymbolAddress((void**)&cw,     g_cw);
    cudaGetSymbolAddress((void**)&qmT,    g_qmT);
    cudaGetSymbolAddress((void**)&sim,    g_sim);
    cudaGetSymbolAddress((void**)&rowmax, g_rowmax);
    cudaGetSymbolAddress((void**)&cwsoft, g_cwsoft);
    cudaGetSymbolAddress((void**)&q2c,    g_q2c);
    cudaGetSymbolAddress((void**)&c2q,    g_c2q);
    cudaGetSymbolAddress((void**)&att,    g_att);
    cudaGetSymbolAddress((void**)&h,      g_h);

    // q_w[b,q], c_w[b,c]
    rows_dot_kernel<<<BB * QQ / 8, 256>>>(question, w_q, qw, EE);
    rows_dot_kernel<<<BB * CC / 8, 256>>>(context, w_c, cw, EE);

    // qmT[b,e,q] = question[b,q,e]*w_m[e]
    make_qmT_kernel<<<dim3(QQ / 32, EE / 32, BB), dim3(32, 8)>>>(question, w_m, qmT);

    // sim[b,c,q] = ctx @ qmT + c_w[row] + q_w[col]
    gemm128<1><<<dim3(QQ / 128, CC / 128, BB), 256>>>(
        context, qmT, sim, CC, QQ, EE,
        (long)CC * EE, (long)EE * QQ, (long)CC * QQ, cw, CC, qw, QQ);

    // softmax over q (in-place) + rowmax
    softmax_q_kernel<<<BB * CC / 8, 256>>>(sim, rowmax);

    // softmax over c, then q2c
    softmax_c_kernel<<<BB, 256>>>(rowmax, cwsoft);
    q2c_kernel<<<BB * EE / 256, 256>>>(context, cwsoft, q2c);

    // c2q[b,c,e] = P @ question
    gemm128<0><<<dim3(EE / 128, CC / 128, BB), 256>>>(
        sim, question, c2q, CC, EE, QQ,
        (long)CC * QQ, (long)QQ * EE, (long)CC * EE, nullptr, 0, nullptr, 0);

    // attended
    build_att_kernel<<<(BB * CC * FE) / 256, 256>>>(context, c2q, q2c, att);

    // h = (att @ W1 + b1) * mask
    gemm128<2><<<dim3(HH / 128, BB * CC / 128, 1), 256>>>(
        att, W1, h, BB * CC, HH, FE, 0, 0, 0, b1, 0, mask, 0);

    // out = relu((h @ W2 + b2) * mask)
    gemm128<3><<<dim3(FE / 128, BB * CC / 128, 1), 256>>>(
        h, W2, out, BB * CC, FE, HH, 0, 0, 0, b2, 0, mask, 0);
}

// round 6
// speedup vs baseline: 2.0742x; 2.0742x over previous
#include <cuda_runtime.h>
#include <cuda_bf16.h>
#include <math.h>
#include <stdint.h>

#define BB 8
#define CC 1024
#define QQ 128
#define EE 512
#define HH 1024
#define FE 2048  /* 4*E */

// ------- scratch (static device globals; 256B-aligned for cp.async/float4) ---
__device__ __align__(256) float g_qw[BB * QQ];
__device__ __align__(256) float g_cw[BB * CC];
__device__ __align__(256) float g_qmT[BB * EE * QQ];
__device__ __align__(256) float g_sim[BB * CC * QQ];   // reused as softmax probs P
__device__ __align__(256) float g_rowmax[BB * CC];
__device__ __align__(256) float g_cwsoft[BB * CC];
__device__ __align__(256) float g_q2c[BB * EE];
__device__ __align__(256) float g_c2q[BB * CC * EE];

__device__ __align__(256) __nv_bfloat16 g_att_hi[(size_t)BB * CC * FE];
__device__ __align__(256) __nv_bfloat16 g_att_lo[(size_t)BB * CC * FE];
__device__ __align__(256) __nv_bfloat16 g_w1t_hi[(size_t)HH * FE];   // [N=HH, K=FE]
__device__ __align__(256) __nv_bfloat16 g_w1t_lo[(size_t)HH * FE];
__device__ __align__(256) __nv_bfloat16 g_w2t_hi[(size_t)FE * HH];   // [N=FE, K=HH]
__device__ __align__(256) __nv_bfloat16 g_w2t_lo[(size_t)FE * HH];
__device__ __align__(256) __nv_bfloat16 g_h_hi[(size_t)BB * CC * HH];
__device__ __align__(256) __nv_bfloat16 g_h_lo[(size_t)BB * CC * HH];

// ---------------- small helpers ---------------------------------------------
__device__ __forceinline__ float warp_sum(float v) {
    #pragma unroll
    for (int o = 16; o > 0; o >>= 1) v += __shfl_xor_sync(0xFFFFFFFFu, v, o);
    return v;
}
__device__ __forceinline__ float warp_max(float v) {
    #pragma unroll
    for (int o = 16; o > 0; o >>= 1) v = fmaxf(v, __shfl_xor_sync(0xFFFFFFFFu, v, o));
    return v;
}
__device__ __forceinline__ uint32_t s2u(const void* p) {
    uint32_t a;
    asm("{ .reg .u64 t; cvta.to.shared.u64 t, %1; cvt.u32.u64 %0, t; }"
        : "=r"(a) : "l"(p));
    return a;
}
__device__ __forceinline__ void cpa16(uint32_t d, const void* s) {
    asm volatile("cp.async.cg.shared.global [%0], [%1], 16;" :: "r"(d), "l"(s));
}
#define CP_COMMIT() asm volatile("cp.async.commit_group;" ::: "memory")
#define CP_WAIT(N)  asm volatile("cp.async.wait_group %0;" :: "n"(N) : "memory")

__device__ __forceinline__ void ldsm4(uint32_t* r, uint32_t addr) {
    asm volatile("ldmatrix.sync.aligned.m8n8.x4.shared.b16 {%0,%1,%2,%3}, [%4];"
                 : "=r"(r[0]), "=r"(r[1]), "=r"(r[2]), "=r"(r[3]) : "r"(addr));
}
__device__ __forceinline__ void mma16816(float* c, const uint32_t* a,
                                         const uint32_t* b) {
    asm volatile(
        "mma.sync.aligned.m16n8k16.row.col.f32.bf16.bf16.f32 "
        "{%0,%1,%2,%3}, {%4,%5,%6,%7}, {%8,%9}, {%0,%1,%2,%3};"
        : "+f"(c[0]), "+f"(c[1]), "+f"(c[2]), "+f"(c[3])
        : "r"(a[0]), "r"(a[1]), "r"(a[2]), "r"(a[3]), "r"(b[0]), "r"(b[1]));
}

// ========================= mma.sync GEMM =====================================
// C[M,N] = (Ahi+Alo)[M,K] @ (Bhi+Blo)[N,K]^T with fp32 accum (3-term split).
// Tile 128x128, K-chunk 32, 2-stage cp.async pipeline.
// MODE 1: h = (acc + bias[col]) * mask[row]  -> bf16 hi/lo pair
// MODE 2: out = relu((acc + bias[col]) * mask[row]) -> fp32
#define TS 80            /* smem row stride bytes (32 bf16 + pad) */
#define MATB (128 * TS)  /* 10240 bytes per matrix tile */
#define STG (4 * MATB)   /* 40960 bytes per stage: Ahi,Alo,Bhi,Blo */
#define SMEM_DYN (2 * STG)

template <int MODE>
__global__ void __launch_bounds__(256) tgemm(
    const __nv_bfloat16* __restrict__ Ahi, const __nv_bfloat16* __restrict__ Alo,
    const __nv_bfloat16* __restrict__ Bhi, const __nv_bfloat16* __restrict__ Blo,
    __nv_bfloat16* __restrict__ Ohi, __nv_bfloat16* __restrict__ Olo,
    float* __restrict__ Ofp, int K, int Nt,
    const float* __restrict__ bias, const float* __restrict__ mask) {
    extern __shared__ char sm[];
    uint32_t sb = s2u(sm);
    int tid = threadIdx.x, wid = tid >> 5, lane = tid & 31;
    int rowBase = blockIdx.y * 128, colBase = blockIdx.x * 128;
    int wm = wid & 3, wn = wid >> 2;

    // ldmatrix per-lane base offsets
    uint32_t aBaseOff = (uint32_t)(wm * 32 + (lane & 15)) * TS + ((lane >> 4) << 4);
    uint32_t bBaseOff = 2 * MATB +
        (uint32_t)(wn * 64 + (lane & 7) + ((lane >> 4) << 3)) * TS +
        (((lane >> 3) & 1) << 4);

    float acc[2][8][4];
    #pragma unroll
    for (int i = 0; i < 2; i++)
        #pragma unroll
        for (int j = 0; j < 8; j++)
            #pragma unroll
            for (int k = 0; k < 4; k++) acc[i][j][k] = 0.f;

    const char* pAhi = (const char*)Ahi;
    const char* pAlo = (const char*)Alo;
    const char* pBhi = (const char*)Bhi;
    const char* pBlo = (const char*)Blo;
    long Kb = (long)K * 2;

    auto load_stage = [&](int st, int kc) {
        uint32_t base = sb + st * STG;
        long koff = (long)kc * 64;
        #pragma unroll
        for (int i = 0; i < 2; i++) {
            int c = tid + (i << 8);
            int r = c >> 2, f = c & 3;
            uint32_t doff = (uint32_t)r * TS + (f << 4);
            long aoff = (long)(rowBase + r) * Kb + koff + (f << 4);
            long boff = (long)(colBase + r) * Kb + koff + (f << 4);
            cpa16(base + doff,            pAhi + aoff);
            cpa16(base + MATB + doff,     pAlo + aoff);
            cpa16(base + 2 * MATB + doff, pBhi + boff);
            cpa16(base + 3 * MATB + doff, pBlo + boff);
        }
    };

    auto compute_stage = [&](int st) {
        uint32_t abase = sb + st * STG + aBaseOff;
        uint32_t bbase = sb + st * STG + bBaseOff;
        #pragma unroll
        for (int ks = 0; ks < 2; ks++) {
            uint32_t ah[2][4], al[2][4];
            #pragma unroll
            for (int mi = 0; mi < 2; mi++) {
                uint32_t aa = abase + mi * (16 * TS) + ks * 32;
                ldsm4(ah[mi], aa);
                ldsm4(al[mi], aa + MATB);
            }
            #pragma unroll
            for (int t4 = 0; t4 < 4; t4++) {
                uint32_t bh[4], bl[4];
                uint32_t ba = bbase + t4 * (16 * TS) + ks * 32;
                ldsm4(bh, ba);
                ldsm4(bl, ba + MATB);
                #pragma unroll
                for (int mi = 0; mi < 2; mi++)
                    #pragma unroll
                    for (int h = 0; h < 2; h++) {
                        float* c = acc[mi][t4 * 2 + h];
                        mma16816(c, ah[mi], bh + 2 * h);
                        mma16816(c, ah[mi], bl + 2 * h);
                        mma16816(c, al[mi], bh + 2 * h);
                    }
            }
        }
    };

    int nch = K >> 5;
    load_stage(0, 0);
    CP_COMMIT();
    for (int kc = 0; kc < nch; kc++) {
        int st = kc & 1;
        if (kc + 1 < nch) {
            load_stage(st ^ 1, kc + 1);
            CP_COMMIT();
            CP_WAIT(1);
        } else {
            CP_WAIT(0);
        }
        __syncthreads();
        compute_stage(st);
        __syncthreads();
    }

    // epilogue straight from registers
    #pragma unroll
    for (int mi = 0; mi < 2; mi++) {
        int r0 = rowBase + wm * 32 + mi * 16 + (lane >> 2);
        int r1 = r0 + 8;
        float mk0 = mask[r0], mk1 = mask[r1];
        #pragma unroll
        for (int ni = 0; ni < 8; ni++) {
            int col = colBase + wn * 64 + ni * 8 + (lane & 3) * 2;
            float bv0 = bias[col], bv1 = bias[col + 1];
            float v0 = (acc[mi][ni][0] + bv0) * mk0;
            float v1 = (acc[mi][ni][1] + bv1) * mk0;
            float v2 = (acc[mi][ni][2] + bv0) * mk1;
            float v3 = (acc[mi][ni][3] + bv1) * mk1;
            size_t o0 = (size_t)r0 * Nt + col;
            size_t o1 = (size_t)r1 * Nt + col;
            if (MODE == 2) {
                *(float2*)(Ofp + o0) = make_float2(fmaxf(v0, 0.f), fmaxf(v1, 0.f));
                *(float2*)(Ofp + o1) = make_float2(fmaxf(v2, 0.f), fmaxf(v3, 0.f));
            } else {
                __nv_bfloat16 h0 = __float2bfloat16(v0);
                __nv_bfloat16 h1 = __float2bfloat16(v1);
                __nv_bfloat16 h2 = __float2bfloat16(v2);
                __nv_bfloat16 h3 = __float2bfloat16(v3);
                *(__nv_bfloat162*)(Ohi + o0) = __halves2bfloat162(h0, h1);
                *(__nv_bfloat162*)(Ohi + o1) = __halves2bfloat162(h2, h3);
                __nv_bfloat16 l0 = __float2bfloat16(v0 - __bfloat162float(h0));
                __nv_bfloat16 l1 = __float2bfloat16(v1 - __bfloat162float(h1));
                __nv_bfloat16 l2 = __float2bfloat16(v2 - __bfloat162float(h2));
                __nv_bfloat16 l3 = __float2bfloat16(v3 - __bfloat162float(h3));
                *(__nv_bfloat162*)(Olo + o0) = __halves2bfloat162(l0, l1);
                *(__nv_bfloat162*)(Olo + o1) = __halves2bfloat162(l2, l3);
            }
        }
    }
}

// ---------------- W transpose + bf16 hi/lo split -----------------------------
// W[K,N] row-major -> T_hi/T_lo [N,K]
__global__ void transW(const float* __restrict__ W, __nv_bfloat16* __restrict__ Thi,
                       __nv_bfloat16* __restrict__ Tlo, int K, int N) {
    __shared__ float t[32][33];
    int k0 = blockIdx.x * 32, n0 = blockIdx.y * 32;
    int tx = threadIdx.x, ty = threadIdx.y;   // 32 x 8
    #pragma unroll
    for (int i = 0; i < 4; i++)
        t[ty + i * 8][tx] = W[(size_t)(k0 + ty + i * 8) * N + n0 + tx];
    __syncthreads();
    #pragma unroll
    for (int i = 0; i < 4; i++) {
        float v = t[tx][ty + i * 8];          // W[k0+tx][n0+ty+i*8]
        int n = n0 + ty + i * 8, k = k0 + tx;
        __nv_bfloat16 h = __float2bfloat16(v);
        __nv_bfloat16 l = __float2bfloat16(v - __bfloat162float(h));
        Thi[(size_t)n * K + k] = h;
        Tlo[(size_t)n * K + k] = l;
    }
}

// out[row] = dot(X[row,:], w)  — warp per row, E multiple of 128
__global__ void rows_dot_kernel(const float* __restrict__ X,
                                const float* __restrict__ w,
                                float* __restrict__ out, int E) {
    int row  = blockIdx.x * 8 + (threadIdx.x >> 5);
    int lane = threadIdx.x & 31;
    const float4* x  = (const float4*)(X + (long)row * E);
    const float4* wv = (const float4*)w;
    float s = 0.f;
    for (int i = lane; i * 4 < E; i += 32) {
        float4 a = x[i], b = wv[i];
        s += a.x * b.x + a.y * b.y + a.z * b.z + a.w * b.w;
    }
    s = warp_sum(s);
    if (lane == 0) out[row] = s;
}

// qmT[b,e,q] = question[b,q,e] * w_mult[e]   (tiled transpose)
__global__ void make_qmT_kernel(const float* __restrict__ question,
                                const float* __restrict__ wm,
                                float* __restrict__ qmT) {
    __shared__ float t[32][33];
    int b  = blockIdx.z;
    int q0 = blockIdx.x * 32, e0 = blockIdx.y * 32;
    int tx = threadIdx.x, ty = threadIdx.y;   // 32 x 8
    #pragma unroll
    for (int i = 0; i < 4; i++)
        t[ty + i * 8][tx] =
            question[((long)b * QQ + q0 + ty + i * 8) * EE + e0 + tx] * wm[e0 + tx];
    __syncthreads();
    #pragma unroll
    for (int i = 0; i < 4; i++)
        qmT[((long)b * EE + e0 + ty + i * 8) * QQ + q0 + tx] = t[tx][ty + i * 8];
}

// ---------------- generic 128x128x16 tiled fp32 GEMM (small GEMMs) -----------
// MODE 0: C = acc
// MODE 1: C = acc + aux1[z*a1s + row] + aux2[z*a2s + col]          (sim)
template <int MODE>
__global__ void __launch_bounds__(256) gemm128(
    const float* __restrict__ A, const float* __restrict__ B, float* __restrict__ C,
    int M, int N, int K, long sA, long sB, long sC,
    const float* __restrict__ aux1, int a1s,
    const float* __restrict__ aux2, int a2s) {
    __shared__ float As[16][128];
    __shared__ float Bs[16][128];
    int z = blockIdx.z;
    A += (long)z * sA; B += (long)z * sB; C += (long)z * sC;

    int tid = threadIdx.x;
    int tx = tid & 15, ty = tid >> 4;
    int rowBase = blockIdx.y * 128;
    int colBase = blockIdx.x * 128;

    int aRow = tid >> 2;
    int aCol = (tid & 3) << 2;
    int bRow = tid >> 5;
    int bCol = (tid & 31) << 2;

    float acc[8][8];
    #pragma unroll
    for (int i = 0; i < 8; i++)
        #pragma unroll
        for (int j = 0; j < 8; j++) acc[i][j] = 0.f;

    for (int k0 = 0; k0 < K; k0 += 16) {
        #pragma unroll
        for (int i = 0; i < 2; i++) {
            float4 v = *(const float4*)(A + (long)(rowBase + aRow + i * 64) * K + k0 + aCol);
            As[aCol + 0][aRow + i * 64] = v.x;
            As[aCol + 1][aRow + i * 64] = v.y;
            As[aCol + 2][aRow + i * 64] = v.z;
            As[aCol + 3][aRow + i * 64] = v.w;
        }
        #pragma unroll
        for (int i = 0; i < 2; i++) {
            float4 v = *(const float4*)(B + (long)(k0 + bRow + i * 8) * N + colBase + bCol);
            *(float4*)&Bs[bRow + i * 8][bCol] = v;
        }
        __syncthreads();
        #pragma unroll
        for (int kk = 0; kk < 16; kk++) {
            float a[8], bb[8];
            #pragma unroll
            for (int i = 0; i < 4; i++) {
                a[i]      = As[kk][ty * 4 + i];
                a[i + 4]  = As[kk][64 + ty * 4 + i];
                bb[i]     = Bs[kk][tx * 4 + i];
                bb[i + 4] = Bs[kk][64 + tx * 4 + i];
            }
            #pragma unroll
            for (int i = 0; i < 8; i++)
                #pragma unroll
                for (int j = 0; j < 8; j++) acc[i][j] += a[i] * bb[j];
        }
        __syncthreads();
    }

    #pragma unroll
    for (int i = 0; i < 8; i++) {
        int r = rowBase + ((i < 4) ? ty * 4 + i : 64 + ty * 4 + (i - 4));
        #pragma unroll
        for (int j = 0; j < 8; j++) {
            int c = colBase + ((j < 4) ? tx * 4 + j : 64 + tx * 4 + (j - 4));
            float v = acc[i][j];
            if (MODE == 1) v += aux1[z * a1s + r] + aux2[z * a2s + c];
            C[(long)r * N + c] = v;
        }
    }
}

// ---------------- softmax over q (Q=128), warp per row; also rowmax ----------
__global__ void softmax_q_kernel(float* __restrict__ sim, float* __restrict__ rowmax) {
    int row  = blockIdx.x * 8 + (threadIdx.x >> 5);
    int lane = threadIdx.x & 31;
    float4* p = (float4*)(sim + (long)row * QQ);
    float4 v = p[lane];
    float m = fmaxf(fmaxf(v.x, v.y), fmaxf(v.z, v.w));
    m = warp_max(m);
    float ex = __expf(v.x - m), ey = __expf(v.y - m),
          ez = __expf(v.z - m), ew = __expf(v.w - m);
    float s = warp_sum(ex + ey + ez + ew);
    float inv = 1.f / s;
    p[lane] = make_float4(ex * inv, ey * inv, ez * inv, ew * inv);
    if (lane == 0) rowmax[row] = m;
}

// ---------------- softmax over c (C=1024) per batch --------------------------
__global__ void softmax_c_kernel(const float* __restrict__ rowmax,
                                 float* __restrict__ cwsoft) {
    int b   = blockIdx.x;
    int tid = threadIdx.x;
    int wid = tid >> 5, lane = tid & 31;
    __shared__ float redm[8], reds[8];
    float4 v = ((const float4*)(rowmax + b * CC))[tid];
    float m = fmaxf(fmaxf(v.x, v.y), fmaxf(v.z, v.w));
    m = warp_max(m);
    if (lane == 0) redm[wid] = m;
    __syncthreads();
    float bm = redm[0];
    #pragma unroll
    for (int i = 1; i < 8; i++) bm = fmaxf(bm, redm[i]);
    float ex = __expf(v.x - bm), ey = __expf(v.y - bm),
          ez = __expf(v.z - bm), ew = __expf(v.w - bm);
    float s = warp_sum(ex + ey + ez + ew);
    if (lane == 0) reds[wid] = s;
    __syncthreads();
    float bs = 0.f;
    #pragma unroll
    for (int i = 0; i < 8; i++) bs += reds[i];
    float inv = 1.f / bs;
    ((float4*)(cwsoft + b * CC))[tid] =
        make_float4(ex * inv, ey * inv, ez * inv, ew * inv);
}

// ---------------- q2c[b,e] = sum_c cwsoft[b,c]*context[b,c,e] -----------------
__global__ void q2c_kernel(const float* __restrict__ context,
                           const float* __restrict__ cwsoft,
                           float* __restrict__ q2c) {
    int idx = blockIdx.x * 256 + threadIdx.x;
    int b = idx / EE, e = idx % EE;
    const float* ctx = context + (long)b * CC * EE + e;
    const float* w   = cwsoft + b * CC;
    float s = 0.f;
    #pragma unroll 4
    for (int c = 0; c < CC; c++) s += w[c] * ctx[(long)c * EE];
    q2c[idx] = s;
}

// -------- attended = [ctx, c2q, ctx*c2q, ctx*q2c] -> bf16 hi/lo --------------
__global__ void build_att_bf16(const float* __restrict__ ctx,
                               const float* __restrict__ c2q,
                               const float* __restrict__ q2c,
                               __nv_bfloat16* __restrict__ Ahi,
                               __nv_bfloat16* __restrict__ Alo) {
    long idx = (long)blockIdx.x * 256 + threadIdx.x;
    int  k   = (int)(idx & (FE - 1));
    long bc  = idx >> 11;            // / 2048
    int  e   = k & (EE - 1);
    int  seg = k >> 9;
    int  b   = (int)(bc >> 10);      // / 1024
    float cv = ctx[bc * EE + e];
    float v;
    if (seg == 0)       v = cv;
    else if (seg == 3)  v = cv * q2c[b * EE + e];
    else {
        float t = c2q[bc * EE + e];
        v = (seg == 1) ? t : cv * t;
    }
    __nv_bfloat16 h = __float2bfloat16(v);
    __nv_bfloat16 l = __float2bfloat16(v - __bfloat162float(h));
    Ahi[idx] = h;
    Alo[idx] = l;
}

// ---------------- launch -----------------------------------------------------
extern "C" void kernel_launch(void* const* d_in, const int* in_sizes, int n_in,
                              void* d_out, int out_size) {
    const float* context  = (const float*)d_in[0];
    const float* question = (const float*)d_in[1];
    const float* mask     = (const float*)d_in[2];
    const float* w_q      = (const float*)d_in[3];
    const float* w_c      = (const float*)d_in[4];
    const float* w_m      = (const float*)d_in[5];
    const float* W1       = (const float*)d_in[6];
    const float* b1       = (const float*)d_in[7];
    const float* W2       = (const float*)d_in[8];
    const float* b2       = (const float*)d_in[9];
    float* out = (float*)d_out;

    float *qw, *cw, *qmT, *sim, *rowmax, *cwsoft, *q2c, *c2q;
    __nv_bfloat16 *att_hi, *att_lo, *w1t_hi, *w1t_lo, *w2t_hi, *w2t_lo, *h_hi, *h_lo;
    cudaGetSymbolAddress((void**)&qw,     g_qw);
    cudaGetSymbolAddress((void**)&cw,     g_cw);
    cudaGetSymbolAddress((void**)&qmT,    g_qmT);
    cudaGetSymbolAddress((void**)&sim,    g_sim);
    cudaGetSymbolAddress((void**)&rowmax, g_rowmax);
    cudaGetSymbolAddress((void**)&cwsoft, g_cwsoft);
    cudaGetSymbolAddress((void**)&q2c,    g_q2c);
    cudaGetSymbolAddress((void**)&c2q,    g_c2q);
    cudaGetSymbolAddress((void**)&att_hi, g_att_hi);
    cudaGetSymbolAddress((void**)&att_lo, g_att_lo);
    cudaGetSymbolAddress((void**)&w1t_hi, g_w1t_hi);
    cudaGetSymbolAddress((void**)&w1t_lo, g_w1t_lo);
    cudaGetSymbolAddress((void**)&w2t_hi, g_w2t_hi);
    cudaGetSymbolAddress((void**)&w2t_lo, g_w2t_lo);
    cudaGetSymbolAddress((void**)&h_hi,   g_h_hi);
    cudaGetSymbolAddress((void**)&h_lo,   g_h_lo);

    cudaFuncSetAttribute(tgemm<1>, cudaFuncAttributeMaxDynamicSharedMemorySize, SMEM_DYN);
    cudaFuncSetAttribute(tgemm<2>, cudaFuncAttributeMaxDynamicSharedMemorySize, SMEM_DYN);

    // weight transposes + bf16 split (independent of activations)
    transW<<<dim3(FE / 32, HH / 32), dim3(32, 8)>>>(W1, w1t_hi, w1t_lo, FE, HH);
    transW<<<dim3(HH / 32, FE / 32), dim3(32, 8)>>>(W2, w2t_hi, w2t_lo, HH, FE);

    // q_w[b,q], c_w[b,c]
    rows_dot_kernel<<<BB * QQ / 8, 256>>>(question, w_q, qw, EE);
    rows_dot_kernel<<<BB * CC / 8, 256>>>(context, w_c, cw, EE);

    // qmT[b,e,q] = question[b,q,e]*w_m[e]
    make_qmT_kernel<<<dim3(QQ / 32, EE / 32, BB), dim3(32, 8)>>>(question, w_m, qmT);

    // sim[b,c,q] = ctx @ qmT + c_w[row] + q_w[col]
    gemm128<1><<<dim3(QQ / 128, CC / 128, BB), 256>>>(
        context, qmT, sim, CC, QQ, EE,
        (long)CC * EE, (long)EE * QQ, (long)CC * QQ, cw, CC, qw, QQ);

    // softmax over q (in-place) + rowmax
    softmax_q_kernel<<<BB * CC / 8, 256>>>(sim, rowmax);

    // softmax over c, then q2c
    softmax_c_kernel<<<BB, 256>>>(rowmax, cwsoft);
    q2c_kernel<<<BB * EE / 256, 256>>>(context, cwsoft, q2c);

    // c2q[b,c,e] = P @ question
    gemm128<0><<<dim3(EE / 128, CC / 128, BB), 256>>>(
        sim, question, c2q, CC, EE, QQ,
        (long)CC * QQ, (long)QQ * EE, (long)CC * EE, nullptr, 0, nullptr, 0);

    // attended -> bf16 hi/lo
    build_att_bf16<<<(int)(((long)BB * CC * FE) / 256), 256>>>(
        context, c2q, q2c, att_hi, att_lo);

    // h = (att @ W1 + b1) * mask   (bf16 hi/lo output)
    tgemm<1><<<dim3(HH / 128, (BB * CC) / 128), 256, SMEM_DYN>>>(
        att_hi, att_lo, w1t_hi, w1t_lo, h_hi, h_lo, nullptr, FE, HH, b1, mask);

    // out = relu((h @ W2 + b2) * mask)
    tgemm<2><<<dim3(FE / 128, (BB * CC) / 128), 256, SMEM_DYN>>>(
        h_hi, h_lo, w2t_hi, w2t_lo, nullptr, nullptr, out, HH, FE, b2, mask);
}

// round 7
// speedup vs baseline: 2.1415x; 1.0325x over previous
#include <cuda_runtime.h>
#include <cuda_bf16.h>
#include <math.h>
#include <stdint.h>

#define BB 8
#define CC 1024
#define QQ 128
#define EE 512
#define HH 1024
#define FE 2048  /* 4*E */

typedef __nv_bfloat16 bf16;

// ------- scratch (static device globals; 256B-aligned) -----------------------
__device__ __align__(256) float g_qw[BB * QQ];
__device__ __align__(256) float g_cw[BB * CC];
__device__ __align__(256) float g_sim[BB * CC * QQ];
__device__ __align__(256) float g_rowmax[BB * CC];
__device__ __align__(256) float g_cwsoft[BB * CC];
__device__ __align__(256) float g_q2c[BB * EE];
__device__ __align__(256) float g_q2c_part[BB * 8 * EE];

__device__ __align__(256) bf16 g_ctx_hi[(size_t)BB * CC * EE];
__device__ __align__(256) bf16 g_ctx_lo[(size_t)BB * CC * EE];
__device__ __align__(256) bf16 g_qm_hi[(size_t)BB * QQ * EE];
__device__ __align__(256) bf16 g_qm_lo[(size_t)BB * QQ * EE];
__device__ __align__(256) bf16 g_qT_hi[(size_t)BB * EE * QQ];
__device__ __align__(256) bf16 g_qT_lo[(size_t)BB * EE * QQ];
__device__ __align__(256) bf16 g_P_hi[(size_t)BB * CC * QQ];
__device__ __align__(256) bf16 g_P_lo[(size_t)BB * CC * QQ];

__device__ __align__(256) bf16 g_att_hi[(size_t)BB * CC * FE];
__device__ __align__(256) bf16 g_att_lo[(size_t)BB * CC * FE];
__device__ __align__(256) bf16 g_w1t_hi[(size_t)HH * FE];   // [N=HH, K=FE]
__device__ __align__(256) bf16 g_w1t_lo[(size_t)HH * FE];
__device__ __align__(256) bf16 g_w2t_hi[(size_t)FE * HH];   // [N=FE, K=HH]
__device__ __align__(256) bf16 g_w2t_lo[(size_t)FE * HH];
__device__ __align__(256) bf16 g_h_hi[(size_t)BB * CC * HH];
__device__ __align__(256) bf16 g_h_lo[(size_t)BB * CC * HH];

// ---------------- small helpers ---------------------------------------------
__device__ __forceinline__ float warp_sum(float v) {
    #pragma unroll
    for (int o = 16; o > 0; o >>= 1) v += __shfl_xor_sync(0xFFFFFFFFu, v, o);
    return v;
}
__device__ __forceinline__ float warp_max(float v) {
    #pragma unroll
    for (int o = 16; o > 0; o >>= 1) v = fmaxf(v, __shfl_xor_sync(0xFFFFFFFFu, v, o));
    return v;
}
__device__ __forceinline__ uint32_t s2u(const void* p) {
    uint32_t a;
    asm("{ .reg .u64 t; cvta.to.shared.u64 t, %1; cvt.u32.u64 %0, t; }"
        : "=r"(a) : "l"(p));
    return a;
}
__device__ __forceinline__ void cpa16(uint32_t d, const void* s) {
    asm volatile("cp.async.cg.shared.global [%0], [%1], 16;" :: "r"(d), "l"(s));
}
#define CP_COMMIT() asm volatile("cp.async.commit_group;" ::: "memory")
#define CP_WAIT(N)  asm volatile("cp.async.wait_group %0;" :: "n"(N) : "memory")

__device__ __forceinline__ void ldsm4(uint32_t* r, uint32_t addr) {
    asm volatile("ldmatrix.sync.aligned.m8n8.x4.shared.b16 {%0,%1,%2,%3}, [%4];"
                 : "=r"(r[0]), "=r"(r[1]), "=r"(r[2]), "=r"(r[3]) : "r"(addr));
}
__device__ __forceinline__ void mma16816(float* c, const uint32_t* a,
                                         const uint32_t* b) {
    asm volatile(
        "mma.sync.aligned.m16n8k16.row.col.f32.bf16.bf16.f32 "
        "{%0,%1,%2,%3}, {%4,%5,%6,%7}, {%8,%9}, {%0,%1,%2,%3};"
        : "+f"(c[0]), "+f"(c[1]), "+f"(c[2]), "+f"(c[3])
        : "r"(a[0]), "r"(a[1]), "r"(a[2]), "r"(a[3]), "r"(b[0]), "r"(b[1]));
}

// ========================= mma.sync GEMM =====================================
// C[M,N] = (Ahi+Alo)[M,K] @ (Bhi+Blo)[N,K]^T, fp32 accum, 3-term split.
// Tile 128x128, K-chunk 32, 3-stage cp.async pipeline, one sync per chunk.
// MODE 0: sim = acc + cw[z][row] + qw[z][col]              -> fp32
// MODE 1: h   = (acc + bias[col]) * mask[row]              -> bf16 hi/lo
// MODE 2: out = relu((acc + bias[col]) * mask[row])        -> fp32
// MODE 3: c2q epilogue -> writes attended[4 segs] bf16 hi/lo using ctx,q2c
#define TS 80            /* smem row stride bytes (32 bf16 + pad) */
#define MATB (128 * TS)  /* 10240 bytes per matrix tile */
#define STGB (4 * MATB)  /* 40960 bytes per stage: Ahi,Alo,Bhi,Blo */
#define NSTG 3
#define SMEM_DYN (NSTG * STGB)

template <int MODE>
__global__ void __launch_bounds__(256) tgemm(
    const bf16* __restrict__ Ahi, const bf16* __restrict__ Alo,
    const bf16* __restrict__ Bhi, const bf16* __restrict__ Blo,
    int K, long sA, long sB,
    float* __restrict__ Cfp,
    bf16* __restrict__ Ohi, bf16* __restrict__ Olo,
    const float* __restrict__ x0, const float* __restrict__ x1) {
    extern __shared__ char sm[];
    uint32_t sb = s2u(sm);
    int tid = threadIdx.x, wid = tid >> 5, lane = tid & 31;
    int z = blockIdx.z;
    int rowBase = blockIdx.y * 128, colBase = blockIdx.x * 128;
    int wm = wid & 3, wn = wid >> 2;

    const char* pAhi = (const char*)(Ahi + (size_t)z * sA);
    const char* pAlo = (const char*)(Alo + (size_t)z * sA);
    const char* pBhi = (const char*)(Bhi + (size_t)z * sB);
    const char* pBlo = (const char*)(Blo + (size_t)z * sB);
    long Kb = (long)K * 2;

    uint32_t aBaseOff = (uint32_t)(wm * 32 + (lane & 15)) * TS + ((lane >> 4) << 4);
    uint32_t bBaseOff = 2 * MATB +
        (uint32_t)(wn * 64 + (lane & 7) + ((lane >> 4) << 3)) * TS +
        (((lane >> 3) & 1) << 4);

    float acc[2][8][4];
    #pragma unroll
    for (int i = 0; i < 2; i++)
        #pragma unroll
        for (int j = 0; j < 8; j++)
            #pragma unroll
            for (int k = 0; k < 4; k++) acc[i][j][k] = 0.f;

    auto load_stage = [&](int st, int kc) {
        uint32_t base = sb + st * STGB;
        long koff = (long)kc * 64;
        #pragma unroll
        for (int i = 0; i < 2; i++) {
            int c = tid + (i << 8);
            int r = c >> 2, f = c & 3;
            uint32_t doff = (uint32_t)r * TS + (f << 4);
            long aoff = (long)(rowBase + r) * Kb + koff + (f << 4);
            long boff = (long)(colBase + r) * Kb + koff + (f << 4);
            cpa16(base + doff,            pAhi + aoff);
            cpa16(base + MATB + doff,     pAlo + aoff);
            cpa16(base + 2 * MATB + doff, pBhi + boff);
            cpa16(base + 3 * MATB + doff, pBlo + boff);
        }
    };

    auto compute_stage = [&](int st) {
        uint32_t abase = sb + st * STGB + aBaseOff;
        uint32_t bbase = sb + st * STGB + bBaseOff;
        #pragma unroll
        for (int ks = 0; ks < 2; ks++) {
            uint32_t ah[2][4], al[2][4];
            #pragma unroll
            for (int mi = 0; mi < 2; mi++) {
                uint32_t aa = abase + mi * (16 * TS) + ks * 32;
                ldsm4(ah[mi], aa);
                ldsm4(al[mi], aa + MATB);
            }
            #pragma unroll
            for (int t4 = 0; t4 < 4; t4++) {
                uint32_t bh[4], bl[4];
                uint32_t ba = bbase + t4 * (16 * TS) + ks * 32;
                ldsm4(bh, ba);
                ldsm4(bl, ba + MATB);
                #pragma unroll
                for (int mi = 0; mi < 2; mi++)
                    #pragma unroll
                    for (int h = 0; h < 2; h++) {
                        float* c = acc[mi][t4 * 2 + h];
                        mma16816(c, ah[mi], bh + 2 * h);
                        mma16816(c, ah[mi], bl + 2 * h);
                        mma16816(c, al[mi], bh + 2 * h);
                    }
            }
        }
    };

    int nch = K >> 5;
    load_stage(0, 0); CP_COMMIT();
    load_stage(1, 1); CP_COMMIT();
    for (int kc = 0; kc < nch; kc++) {
        int st = kc % NSTG;
        if (kc + 1 < nch) { CP_WAIT(1); } else { CP_WAIT(0); }
        __syncthreads();
        if (kc + 2 < nch) { load_stage((kc + 2) % NSTG, kc + 2); CP_COMMIT(); }
        compute_stage(st);
    }

    // hi/lo split store helper
    auto st2 = [&](size_t off, float a, float b) {
        bf16 ha = __float2bfloat16(a);
        bf16 hb = __float2bfloat16(b);
        *(__nv_bfloat162*)(Ohi + off) = __halves2bfloat162(ha, hb);
        bf16 la = __float2bfloat16(a - __bfloat162float(ha));
        bf16 lb = __float2bfloat16(b - __bfloat162float(hb));
        *(__nv_bfloat162*)(Olo + off) = __halves2bfloat162(la, lb);
    };

    #pragma unroll
    for (int mi = 0; mi < 2; mi++) {
        int r0 = rowBase + wm * 32 + mi * 16 + (lane >> 2);
        int r1 = r0 + 8;
        float mk0 = 0.f, mk1 = 0.f;
        if (MODE == 1 || MODE == 2) { mk0 = x1[r0]; mk1 = x1[r1]; }
        if (MODE == 0) { mk0 = x0[z * CC + r0]; mk1 = x0[z * CC + r1]; }
        #pragma unroll
        for (int ni = 0; ni < 8; ni++) {
            int col = colBase + wn * 64 + ni * 8 + (lane & 3) * 2;
            float a0 = acc[mi][ni][0], a1 = acc[mi][ni][1];
            float a2 = acc[mi][ni][2], a3 = acc[mi][ni][3];
            if (MODE == 0) {
                float q0 = x1[z * QQ + col], q1 = x1[z * QQ + col + 1];
                float* C = Cfp + ((size_t)z * CC) * QQ;
                *(float2*)(C + (size_t)r0 * QQ + col) =
                    make_float2(a0 + mk0 + q0, a1 + mk0 + q1);
                *(float2*)(C + (size_t)r1 * QQ + col) =
                    make_float2(a2 + mk1 + q0, a3 + mk1 + q1);
            } else if (MODE == 3) {
                const float* ctx = x0 + (size_t)z * CC * EE;
                const float* q2b = x1 + (size_t)z * EE;
                float2 ca = *(const float2*)(ctx + (size_t)r0 * EE + col);
                float2 cb = *(const float2*)(ctx + (size_t)r1 * EE + col);
                float2 qv = *(const float2*)(q2b + col);
                size_t o0 = ((size_t)z * CC + r0) * FE + col;
                size_t o1 = ((size_t)z * CC + r1) * FE + col;
                st2(o0,          ca.x,        ca.y);
                st2(o0 + EE,     a0,          a1);
                st2(o0 + 2 * EE, ca.x * a0,   ca.y * a1);
                st2(o0 + 3 * EE, ca.x * qv.x, ca.y * qv.y);
                st2(o1,          cb.x,        cb.y);
                st2(o1 + EE,     a2,          a3);
                st2(o1 + 2 * EE, cb.x * a2,   cb.y * a3);
                st2(o1 + 3 * EE, cb.x * qv.x, cb.y * qv.y);
            } else {
                float bv0 = x0[col], bv1 = x0[col + 1];
                float v0 = (a0 + bv0) * mk0;
                float v1 = (a1 + bv1) * mk0;
                float v2 = (a2 + bv0) * mk1;
                float v3 = (a3 + bv1) * mk1;
                if (MODE == 2) {
                    size_t o0 = (size_t)r0 * FE + col;
                    size_t o1 = (size_t)r1 * FE + col;
                    *(float2*)(Cfp + o0) = make_float2(fmaxf(v0, 0.f), fmaxf(v1, 0.f));
                    *(float2*)(Cfp + o1) = make_float2(fmaxf(v2, 0.f), fmaxf(v3, 0.f));
                } else {
                    size_t o0 = (size_t)r0 * HH + col;
                    size_t o1 = (size_t)r1 * HH + col;
                    st2(o0, v0, v1);
                    st2(o1, v2, v3);
                }
            }
        }
    }
}

// ---------------- W transpose + bf16 hi/lo split -----------------------------
__global__ void transW(const float* __restrict__ W, bf16* __restrict__ Thi,
                       bf16* __restrict__ Tlo, int K, int N) {
    __shared__ float t[32][33];
    int k0 = blockIdx.x * 32, n0 = blockIdx.y * 32;
    int tx = threadIdx.x, ty = threadIdx.y;   // 32 x 8
    #pragma unroll
    for (int i = 0; i < 4; i++)
        t[ty + i * 8][tx] = W[(size_t)(k0 + ty + i * 8) * N + n0 + tx];
    __syncthreads();
    #pragma unroll
    for (int i = 0; i < 4; i++) {
        float v = t[tx][ty + i * 8];
        int n = n0 + ty + i * 8, k = k0 + tx;
        bf16 h = __float2bfloat16(v);
        bf16 l = __float2bfloat16(v - __bfloat162float(h));
        Thi[(size_t)n * K + k] = h;
        Tlo[(size_t)n * K + k] = l;
    }
}

// question^T -> qT_hi/lo [b,e,q]
__global__ void make_qT(const float* __restrict__ question,
                        bf16* __restrict__ Thi, bf16* __restrict__ Tlo) {
    __shared__ float t[32][33];
    int b = blockIdx.z;
    int q0 = blockIdx.x * 32, e0 = blockIdx.y * 32;
    int tx = threadIdx.x, ty = threadIdx.y;
    #pragma unroll
    for (int i = 0; i < 4; i++)
        t[ty + i * 8][tx] = question[((size_t)b * QQ + q0 + ty + i * 8) * EE + e0 + tx];
    __syncthreads();
    #pragma unroll
    for (int i = 0; i < 4; i++) {
        float v = t[tx][ty + i * 8];
        size_t o = ((size_t)b * EE + e0 + ty + i * 8) * QQ + q0 + tx;
        bf16 h = __float2bfloat16(v);
        Thi[o] = h;
        Tlo[o] = __float2bfloat16(v - __bfloat162float(h));
    }
}

// elementwise fp32 -> bf16 hi/lo (4 per thread)
__global__ void split4(const float* __restrict__ src, bf16* __restrict__ hi,
                       bf16* __restrict__ lo) {
    size_t i = ((size_t)blockIdx.x * 256 + threadIdx.x) * 4;
    float4 v = *(const float4*)(src + i);
    bf16 h0 = __float2bfloat16(v.x), h1 = __float2bfloat16(v.y);
    bf16 h2 = __float2bfloat16(v.z), h3 = __float2bfloat16(v.w);
    *(__nv_bfloat162*)(hi + i)     = __halves2bfloat162(h0, h1);
    *(__nv_bfloat162*)(hi + i + 2) = __halves2bfloat162(h2, h3);
    bf16 l0 = __float2bfloat16(v.x - __bfloat162float(h0));
    bf16 l1 = __float2bfloat16(v.y - __bfloat162float(h1));
    bf16 l2 = __float2bfloat16(v.z - __bfloat162float(h2));
    bf16 l3 = __float2bfloat16(v.w - __bfloat162float(h3));
    *(__nv_bfloat162*)(lo + i)     = __halves2bfloat162(l0, l1);
    *(__nv_bfloat162*)(lo + i + 2) = __halves2bfloat162(l2, l3);
}

// qm = question * w_mult -> bf16 hi/lo [b,q,e]
__global__ void make_qm(const float* __restrict__ question,
                        const float* __restrict__ wmv,
                        bf16* __restrict__ hi, bf16* __restrict__ lo) {
    size_t i = ((size_t)blockIdx.x * 256 + threadIdx.x) * 4;
    int e = (int)(i & (EE - 1));
    float4 q = *(const float4*)(question + i);
    float4 w = *(const float4*)(wmv + e);
    float v0 = q.x * w.x, v1 = q.y * w.y, v2 = q.z * w.z, v3 = q.w * w.w;
    bf16 h0 = __float2bfloat16(v0), h1 = __float2bfloat16(v1);
    bf16 h2 = __float2bfloat16(v2), h3 = __float2bfloat16(v3);
    *(__nv_bfloat162*)(hi + i)     = __halves2bfloat162(h0, h1);
    *(__nv_bfloat162*)(hi + i + 2) = __halves2bfloat162(h2, h3);
    bf16 l0 = __float2bfloat16(v0 - __bfloat162float(h0));
    bf16 l1 = __float2bfloat16(v1 - __bfloat162float(h1));
    bf16 l2 = __float2bfloat16(v2 - __bfloat162float(h2));
    bf16 l3 = __float2bfloat16(v3 - __bfloat162float(h3));
    *(__nv_bfloat162*)(lo + i)     = __halves2bfloat162(l0, l1);
    *(__nv_bfloat162*)(lo + i + 2) = __halves2bfloat162(l2, l3);
}

// out[row] = dot(X[row,:], w)
__global__ void rows_dot_kernel(const float* __restrict__ X,
                                const float* __restrict__ w,
                                float* __restrict__ out, int E) {
    int row  = blockIdx.x * 8 + (threadIdx.x >> 5);
    int lane = threadIdx.x & 31;
    const float4* x  = (const float4*)(X + (long)row * E);
    const float4* wv = (const float4*)w;
    float s = 0.f;
    for (int i = lane; i * 4 < E; i += 32) {
        float4 a = x[i], b = wv[i];
        s += a.x * b.x + a.y * b.y + a.z * b.z + a.w * b.w;
    }
    s = warp_sum(s);
    if (lane == 0) out[row] = s;
}

// ------- softmax over q (Q=128): writes P bf16 hi/lo + rowmax ----------------
__global__ void softmax_q_kernel(const float* __restrict__ sim,
                                 bf16* __restrict__ Phi, bf16* __restrict__ Plo,
                                 float* __restrict__ rowmax) {
    int row  = blockIdx.x * 8 + (threadIdx.x >> 5);
    int lane = threadIdx.x & 31;
    const float4* p = (const float4*)(sim + (size_t)row * QQ);
    float4 v = p[lane];
    float m = fmaxf(fmaxf(v.x, v.y), fmaxf(v.z, v.w));
    m = warp_max(m);
    float ex = __expf(v.x - m), ey = __expf(v.y - m),
          ez = __expf(v.z - m), ew = __expf(v.w - m);
    float s = warp_sum(ex + ey + ez + ew);
    float inv = 1.f / s;
    float p0 = ex * inv, p1 = ey * inv, p2 = ez * inv, p3 = ew * inv;
    size_t o = (size_t)row * QQ + lane * 4;
    bf16 h0 = __float2bfloat16(p0), h1 = __float2bfloat16(p1);
    bf16 h2 = __float2bfloat16(p2), h3 = __float2bfloat16(p3);
    *(__nv_bfloat162*)(Phi + o)     = __halves2bfloat162(h0, h1);
    *(__nv_bfloat162*)(Phi + o + 2) = __halves2bfloat162(h2, h3);
    bf16 l0 = __float2bfloat16(p0 - __bfloat162float(h0));
    bf16 l1 = __float2bfloat16(p1 - __bfloat162float(h1));
    bf16 l2 = __float2bfloat16(p2 - __bfloat162float(h2));
    bf16 l3 = __float2bfloat16(p3 - __bfloat162float(h3));
    *(__nv_bfloat162*)(Plo + o)     = __halves2bfloat162(l0, l1);
    *(__nv_bfloat162*)(Plo + o + 2) = __halves2bfloat162(l2, l3);
    if (lane == 0) rowmax[row] = m;
}

// ---------------- softmax over c (C=1024) per batch --------------------------
__global__ void softmax_c_kernel(const float* __restrict__ rowmax,
                                 float* __restrict__ cwsoft) {
    int b   = blockIdx.x;
    int tid = threadIdx.x;
    int wid = tid >> 5, lane = tid & 31;
    __shared__ float redm[8], reds[8];
    float4 v = ((const float4*)(rowmax + b * CC))[tid];
    float m = fmaxf(fmaxf(v.x, v.y), fmaxf(v.z, v.w));
    m = warp_max(m);
    if (lane == 0) redm[wid] = m;
    __syncthreads();
    float bm = redm[0];
    #pragma unroll
    for (int i = 1; i < 8; i++) bm = fmaxf(bm, redm[i]);
    float ex = __expf(v.x - bm), ey = __expf(v.y - bm),
          ez = __expf(v.z - bm), ew = __expf(v.w - bm);
    float s = warp_sum(ex + ey + ez + ew);
    if (lane == 0) reds[wid] = s;
    __syncthreads();
    float bs = 0.f;
    #pragma unroll
    for (int i = 0; i < 8; i++) bs += reds[i];
    float inv = 1.f / bs;
    ((float4*)(cwsoft + b * CC))[tid] =
        make_float4(ex * inv, ey * inv, ez * inv, ew * inv);
}

// ------- q2c: partial over c-chunks then reduce ------------------------------
__global__ void q2c_part_kernel(const float* __restrict__ context,
                                const float* __restrict__ cwsoft,
                                float* __restrict__ part) {
    int b = blockIdx.y, ch = blockIdx.x, e = threadIdx.x;   // 512 threads
    const float* ctx = context + ((size_t)b * CC + ch * 128) * EE + e;
    const float* w   = cwsoft + b * CC + ch * 128;
    float s = 0.f;
    #pragma unroll 4
    for (int c = 0; c < 128; c++) s += w[c] * ctx[(size_t)c * EE];
    part[((size_t)b * 8 + ch) * EE + e] = s;
}
__global__ void q2c_reduce_kernel(const float* __restrict__ part,
                                  float* __restrict__ q2c) {
    int idx = blockIdx.x * 256 + threadIdx.x;   // B*E
    int b = idx / EE, e = idx % EE;
    float s = 0.f;
    #pragma unroll
    for (int ch = 0; ch < 8; ch++) s += part[((size_t)b * 8 + ch) * EE + e];
    q2c[idx] = s;
}

// ---------------- launch -----------------------------------------------------
extern "C" void kernel_launch(void* const* d_in, const int* in_sizes, int n_in,
                              void* d_out, int out_size) {
    const float* context  = (const float*)d_in[0];
    const float* question = (const float*)d_in[1];
    const float* mask     = (const float*)d_in[2];
    const float* w_q      = (const float*)d_in[3];
    const float* w_c      = (const float*)d_in[4];
    const float* w_m      = (const float*)d_in[5];
    const float* W1       = (const float*)d_in[6];
    const float* b1       = (const float*)d_in[7];
    const float* W2       = (const float*)d_in[8];
    const float* b2       = (const float*)d_in[9];
    float* out = (float*)d_out;

    float *qw, *cw, *sim, *rowmax, *cwsoft, *q2c, *q2cp;
    bf16 *ctx_hi, *ctx_lo, *qm_hi, *qm_lo, *qT_hi, *qT_lo, *P_hi, *P_lo;
    bf16 *att_hi, *att_lo, *w1t_hi, *w1t_lo, *w2t_hi, *w2t_lo, *h_hi, *h_lo;
    cudaGetSymbolAddress((void**)&qw,     g_qw);
    cudaGetSymbolAddress((void**)&cw,     g_cw);
    cudaGetSymbolAddress((void**)&sim,    g_sim);
    cudaGetSymbolAddress((void**)&rowmax, g_rowmax);
    cudaGetSymbolAddress((void**)&cwsoft, g_cwsoft);
    cudaGetSymbolAddress((void**)&q2c,    g_q2c);
    cudaGetSymbolAddress((void**)&q2cp,   g_q2c_part);
    cudaGetSymbolAddress((void**)&ctx_hi, g_ctx_hi);
    cudaGetSymbolAddress((void**)&ctx_lo, g_ctx_lo);
    cudaGetSymbolAddress((void**)&qm_hi,  g_qm_hi);
    cudaGetSymbolAddress((void**)&qm_lo,  g_qm_lo);
    cudaGetSymbolAddress((void**)&qT_hi,  g_qT_hi);
    cudaGetSymbolAddress((void**)&qT_lo,  g_qT_lo);
    cudaGetSymbolAddress((void**)&P_hi,   g_P_hi);
    cudaGetSymbolAddress((void**)&P_lo,   g_P_lo);
    cudaGetSymbolAddress((void**)&att_hi, g_att_hi);
    cudaGetSymbolAddress((void**)&att_lo, g_att_lo);
    cudaGetSymbolAddress((void**)&w1t_hi, g_w1t_hi);
    cudaGetSymbolAddress((void**)&w1t_lo, g_w1t_lo);
    cudaGetSymbolAddress((void**)&w2t_hi, g_w2t_hi);
    cudaGetSymbolAddress((void**)&w2t_lo, g_w2t_lo);
    cudaGetSymbolAddress((void**)&h_hi,   g_h_hi);
    cudaGetSymbolAddress((void**)&h_lo,   g_h_lo);

    cudaFuncSetAttribute(tgemm<0>, cudaFuncAttributeMaxDynamicSharedMemorySize, SMEM_DYN);
    cudaFuncSetAttribute(tgemm<1>, cudaFuncAttributeMaxDynamicSharedMemorySize, SMEM_DYN);
    cudaFuncSetAttribute(tgemm<2>, cudaFuncAttributeMaxDynamicSharedMemorySize, SMEM_DYN);
    cudaFuncSetAttribute(tgemm<3>, cudaFuncAttributeMaxDynamicSharedMemorySize, SMEM_DYN);

    // independent prep
    transW<<<dim3(FE / 32, HH / 32), dim3(32, 8)>>>(W1, w1t_hi, w1t_lo, FE, HH);
    transW<<<dim3(HH / 32, FE / 32), dim3(32, 8)>>>(W2, w2t_hi, w2t_lo, HH, FE);
    split4<<<(int)(((size_t)BB * CC * EE) / 1024), 256>>>(context, ctx_hi, ctx_lo);
    make_qm<<<(int)(((size_t)BB * QQ * EE) / 1024), 256>>>(question, w_m, qm_hi, qm_lo);
    make_qT<<<dim3(QQ / 32, EE / 32, BB), dim3(32, 8)>>>(question, qT_hi, qT_lo);
    rows_dot_kernel<<<BB * QQ / 8, 256>>>(question, w_q, qw, EE);
    rows_dot_kernel<<<BB * CC / 8, 256>>>(context, w_c, cw, EE);

    // sim[b,c,q] = ctx @ qm^T + cw[row] + qw[col]   (MODE 0)
    tgemm<0><<<dim3(1, CC / 128, BB), 256, SMEM_DYN>>>(
        ctx_hi, ctx_lo, qm_hi, qm_lo, EE, (long)CC * EE, (long)QQ * EE,
        sim, nullptr, nullptr, cw, qw);

    // softmax over q -> P bf16 hi/lo + rowmax
    softmax_q_kernel<<<BB * CC / 8, 256>>>(sim, P_hi, P_lo, rowmax);

    // softmax over c, then q2c
    softmax_c_kernel<<<BB, 256>>>(rowmax, cwsoft);
    q2c_part_kernel<<<dim3(8, BB), 512>>>(context, cwsoft, q2cp);
    q2c_reduce_kernel<<<BB * EE / 256, 256>>>(q2cp, q2c);

    // c2q = P @ question, epilogue builds attended bf16 hi/lo  (MODE 3)
    tgemm<3><<<dim3(EE / 128, CC / 128, BB), 256, SMEM_DYN>>>(
        P_hi, P_lo, qT_hi, qT_lo, QQ, (long)CC * QQ, (long)EE * QQ,
        nullptr, att_hi, att_lo, context, q2c);

    // h = (att @ W1 + b1) * mask   (MODE 1)
    tgemm<1><<<dim3(HH / 128, (BB * CC) / 128, 1), 256, SMEM_DYN>>>(
        att_hi, att_lo, w1t_hi, w1t_lo, FE, 0, 0,
        nullptr, h_hi, h_lo, b1, mask);

    // out = relu((h @ W2 + b2) * mask)   (MODE 2)
    tgemm<2><<<dim3(FE / 128, (BB * CC) / 128, 1), 256, SMEM_DYN>>>(
        h_hi, h_lo, w2t_hi, w2t_lo, HH, 0, 0,
        out, nullptr, nullptr, b2, mask);
}

// round 8
// speedup vs baseline: 3.7672x; 1.7591x over previous
#include <cuda_runtime.h>
#include <cuda_bf16.h>
#include <math.h>
#include <stdint.h>

#define BB 8
#define CC 1024
#define QQ 128
#define EE 512
#define HH 1024
#define FE 2048  /* 4*E */

typedef __nv_bfloat16 bf16;

// ------- scratch (static device globals; 256B-aligned) -----------------------
__device__ __align__(256) float g_qw[BB * QQ];
__device__ __align__(256) float g_cw[BB * CC];
__device__ __align__(256) float g_sim[BB * CC * QQ];
__device__ __align__(256) float g_rowmax[BB * CC];
__device__ __align__(256) float g_cwsoft[BB * CC];
__device__ __align__(256) float g_q2c[BB * EE];
__device__ __align__(256) float g_q2c_part[BB * 8 * EE];

__device__ __align__(256) bf16 g_ctx_hi[(size_t)BB * CC * EE];
__device__ __align__(256) bf16 g_ctx_lo[(size_t)BB * CC * EE];
__device__ __align__(256) bf16 g_qm_hi[(size_t)BB * QQ * EE];
__device__ __align__(256) bf16 g_qm_lo[(size_t)BB * QQ * EE];
__device__ __align__(256) bf16 g_qT_hi[(size_t)BB * EE * QQ];
__device__ __align__(256) bf16 g_qT_lo[(size_t)BB * EE * QQ];
__device__ __align__(256) bf16 g_P_hi[(size_t)BB * CC * QQ];
__device__ __align__(256) bf16 g_P_lo[(size_t)BB * CC * QQ];

__device__ __align__(256) bf16 g_att_hi[(size_t)BB * CC * FE];
__device__ __align__(256) bf16 g_att_lo[(size_t)BB * CC * FE];
__device__ __align__(256) bf16 g_w1t_hi[(size_t)HH * FE];   // [N=HH, K=FE]
__device__ __align__(256) bf16 g_w1t_lo[(size_t)HH * FE];
__device__ __align__(256) bf16 g_w2t_hi[(size_t)FE * HH];   // [N=FE, K=HH]
__device__ __align__(256) bf16 g_w2t_lo[(size_t)FE * HH];
__device__ __align__(256) bf16 g_h_hi[(size_t)BB * CC * HH];
__device__ __align__(256) bf16 g_h_lo[(size_t)BB * CC * HH];

// ---------------- small helpers ---------------------------------------------
__device__ __forceinline__ float warp_sum(float v) {
    #pragma unroll
    for (int o = 16; o > 0; o >>= 1) v += __shfl_xor_sync(0xFFFFFFFFu, v, o);
    return v;
}
__device__ __forceinline__ float warp_max(float v) {
    #pragma unroll
    for (int o = 16; o > 0; o >>= 1) v = fmaxf(v, __shfl_xor_sync(0xFFFFFFFFu, v, o));
    return v;
}
__device__ __forceinline__ uint32_t s2u(const void* p) {
    uint32_t a;
    asm("{ .reg .u64 t; cvta.to.shared.u64 t, %1; cvt.u32.u64 %0, t; }"
        : "=r"(a) : "l"(p));
    return a;
}
__device__ __forceinline__ void cpa16(uint32_t d, const void* s) {
    asm volatile("cp.async.cg.shared.global [%0], [%1], 16;" :: "r"(d), "l"(s));
}
#define CP_COMMIT() asm volatile("cp.async.commit_group;" ::: "memory")
#define CP_WAIT(N)  asm volatile("cp.async.wait_group %0;" :: "n"(N) : "memory")

__device__ __forceinline__ void ldsm4(uint32_t* r, uint32_t addr) {
    asm volatile("ldmatrix.sync.aligned.m8n8.x4.shared.b16 {%0,%1,%2,%3}, [%4];"
                 : "=r"(r[0]), "=r"(r[1]), "=r"(r[2]), "=r"(r[3]) : "r"(addr));
}
__device__ __forceinline__ void mma16816(float* c, const uint32_t* a,
                                         const uint32_t* b) {
    asm volatile(
        "mma.sync.aligned.m16n8k16.row.col.f32.bf16.bf16.f32 "
        "{%0,%1,%2,%3}, {%4,%5,%6,%7}, {%8,%9}, {%0,%1,%2,%3};"
        : "+f"(c[0]), "+f"(c[1]), "+f"(c[2]), "+f"(c[3])
        : "r"(a[0]), "r"(a[1]), "r"(a[2]), "r"(a[3]), "r"(b[0]), "r"(b[1]));
}

// ========================= mma.sync GEMM =====================================
// C[M,N] = (Ahi+Alo)[M,K] @ (Bhi+Blo)[N,K]^T, fp32 accum, 3-term split.
// Tile 128x128, K-chunk 32, 2-stage cp.async pipeline (80KB -> 2 CTAs/SM).
// MODE 0: sim = acc + cw[z][row] + qw[z][col]              -> fp32
// MODE 1: h   = (acc + bias[col]) * mask[row]              -> bf16 hi/lo
// MODE 2: out = relu((acc + bias[col]) * mask[row])        -> fp32
// MODE 3: c2q epilogue -> writes attended[4 segs] bf16 hi/lo using ctx,q2c
#define TS 80            /* smem row stride bytes (32 bf16 + pad) */
#define MATB (128 * TS)  /* 10240 bytes per matrix tile */
#define STGB (4 * MATB)  /* 40960 bytes per stage: Ahi,Alo,Bhi,Blo */
#define NSTG 2
#define SMEM_DYN (NSTG * STGB)

template <int MODE>
__global__ void __launch_bounds__(256) tgemm(
    const bf16* __restrict__ Ahi, const bf16* __restrict__ Alo,
    const bf16* __restrict__ Bhi, const bf16* __restrict__ Blo,
    int K, long sA, long sB,
    float* __restrict__ Cfp,
    bf16* __restrict__ Ohi, bf16* __restrict__ Olo,
    const float* __restrict__ x0, const float* __restrict__ x1) {
    extern __shared__ char sm[];
    uint32_t sb = s2u(sm);
    int tid = threadIdx.x, wid = tid >> 5, lane = tid & 31;
    int z = blockIdx.z;
    int rowBase = blockIdx.y * 128, colBase = blockIdx.x * 128;
    int wm = wid & 3, wn = wid >> 2;

    const char* pAhi = (const char*)(Ahi + (size_t)z * sA);
    const char* pAlo = (const char*)(Alo + (size_t)z * sA);
    const char* pBhi = (const char*)(Bhi + (size_t)z * sB);
    const char* pBlo = (const char*)(Blo + (size_t)z * sB);
    long Kb = (long)K * 2;

    uint32_t aBaseOff = (uint32_t)(wm * 32 + (lane & 15)) * TS + ((lane >> 4) << 4);
    uint32_t bBaseOff = 2 * MATB +
        (uint32_t)(wn * 64 + (lane & 7) + ((lane >> 4) << 3)) * TS +
        (((lane >> 3) & 1) << 4);

    float acc[2][8][4];
    #pragma unroll
    for (int i = 0; i < 2; i++)
        #pragma unroll
        for (int j = 0; j < 8; j++)
            #pragma unroll
            for (int k = 0; k < 4; k++) acc[i][j][k] = 0.f;

    auto load_stage = [&](int st, int kc) {
        uint32_t base = sb + st * STGB;
        long koff = (long)kc * 64;
        #pragma unroll
        for (int i = 0; i < 2; i++) {
            int c = tid + (i << 8);
            int r = c >> 2, f = c & 3;
            uint32_t doff = (uint32_t)r * TS + (f << 4);
            long aoff = (long)(rowBase + r) * Kb + koff + (f << 4);
            long boff = (long)(colBase + r) * Kb + koff + (f << 4);
            cpa16(base + doff,            pAhi + aoff);
            cpa16(base + MATB + doff,     pAlo + aoff);
            cpa16(base + 2 * MATB + doff, pBhi + boff);
            cpa16(base + 3 * MATB + doff, pBlo + boff);
        }
    };

    auto compute_stage = [&](int st) {
        uint32_t abase = sb + st * STGB + aBaseOff;
        uint32_t bbase = sb + st * STGB + bBaseOff;
        #pragma unroll
        for (int ks = 0; ks < 2; ks++) {
            uint32_t ah[2][4], al[2][4];
            #pragma unroll
            for (int mi = 0; mi < 2; mi++) {
                uint32_t aa = abase + mi * (16 * TS) + ks * 32;
                ldsm4(ah[mi], aa);
                ldsm4(al[mi], aa + MATB);
            }
            #pragma unroll
            for (int t4 = 0; t4 < 4; t4++) {
                uint32_t bh[4], bl[4];
                uint32_t ba = bbase + t4 * (16 * TS) + ks * 32;
                ldsm4(bh, ba);
                ldsm4(bl, ba + MATB);
                #pragma unroll
                for (int mi = 0; mi < 2; mi++)
                    #pragma unroll
                    for (int h = 0; h < 2; h++) {
                        float* c = acc[mi][t4 * 2 + h];
                        mma16816(c, ah[mi], bh + 2 * h);
                        mma16816(c, ah[mi], bl + 2 * h);
                        mma16816(c, al[mi], bh + 2 * h);
                    }
            }
        }
    };

    int nch = K >> 5;
    load_stage(0, 0);
    CP_COMMIT();
    for (int kc = 0; kc < nch; kc++) {
        int st = kc & 1;
        if (kc + 1 < nch) {
            load_stage(st ^ 1, kc + 1);
            CP_COMMIT();
            CP_WAIT(1);
        } else {
            CP_WAIT(0);
        }
        __syncthreads();
        compute_stage(st);
        __syncthreads();
    }

    // hi/lo split store helper
    auto st2 = [&](size_t off, float a, float b) {
        bf16 ha = __float2bfloat16(a);
        bf16 hb = __float2bfloat16(b);
        *(__nv_bfloat162*)(Ohi + off) = __halves2bfloat162(ha, hb);
        bf16 la = __float2bfloat16(a - __bfloat162float(ha));
        bf16 lb = __float2bfloat16(b - __bfloat162float(hb));
        *(__nv_bfloat162*)(Olo + off) = __halves2bfloat162(la, lb);
    };

    #pragma unroll
    for (int mi = 0; mi < 2; mi++) {
        int r0 = rowBase + wm * 32 + mi * 16 + (lane >> 2);
        int r1 = r0 + 8;
        float mk0 = 0.f, mk1 = 0.f;
        if (MODE == 1 || MODE == 2) { mk0 = x1[r0]; mk1 = x1[r1]; }
        if (MODE == 0) { mk0 = x0[z * CC + r0]; mk1 = x0[z * CC + r1]; }
        #pragma unroll
        for (int ni = 0; ni < 8; ni++) {
            int col = colBase + wn * 64 + ni * 8 + (lane & 3) * 2;
            float a0 = acc[mi][ni][0], a1 = acc[mi][ni][1];
            float a2 = acc[mi][ni][2], a3 = acc[mi][ni][3];
            if (MODE == 0) {
                float q0 = x1[z * QQ + col], q1 = x1[z * QQ + col + 1];
                float* C = Cfp + ((size_t)z * CC) * QQ;
                *(float2*)(C + (size_t)r0 * QQ + col) =
                    make_float2(a0 + mk0 + q0, a1 + mk0 + q1);
                *(float2*)(C + (size_t)r1 * QQ + col) =
                    make_float2(a2 + mk1 + q0, a3 + mk1 + q1);
            } else if (MODE == 3) {
                const float* ctx = x0 + (size_t)z * CC * EE;
                const float* q2b = x1 + (size_t)z * EE;
                float2 ca = *(const float2*)(ctx + (size_t)r0 * EE + col);
                float2 cb = *(const float2*)(ctx + (size_t)r1 * EE + col);
                float2 qv = *(const float2*)(q2b + col);
                size_t o0 = ((size_t)z * CC + r0) * FE + col;
                size_t o1 = ((size_t)z * CC + r1) * FE + col;
                st2(o0,          ca.x,        ca.y);
                st2(o0 + EE,     a0,          a1);
                st2(o0 + 2 * EE, ca.x * a0,   ca.y * a1);
                st2(o0 + 3 * EE, ca.x * qv.x, ca.y * qv.y);
                st2(o1,          cb.x,        cb.y);
                st2(o1 + EE,     a2,          a3);
                st2(o1 + 2 * EE, cb.x * a2,   cb.y * a3);
                st2(o1 + 3 * EE, cb.x * qv.x, cb.y * qv.y);
            } else {
                float bv0 = x0[col], bv1 = x0[col + 1];
                float v0 = (a0 + bv0) * mk0;
                float v1 = (a1 + bv1) * mk0;
                float v2 = (a2 + bv0) * mk1;
                float v3 = (a3 + bv1) * mk1;
                if (MODE == 2) {
                    size_t o0 = (size_t)r0 * FE + col;
                    size_t o1 = (size_t)r1 * FE + col;
                    *(float2*)(Cfp + o0) = make_float2(fmaxf(v0, 0.f), fmaxf(v1, 0.f));
                    *(float2*)(Cfp + o1) = make_float2(fmaxf(v2, 0.f), fmaxf(v3, 0.f));
                } else {
                    size_t o0 = (size_t)r0 * HH + col;
                    size_t o1 = (size_t)r1 * HH + col;
                    st2(o0, v0, v1);
                    st2(o1, v2, v3);
                }
            }
        }
    }
}

// ---------------- W transpose + bf16 hi/lo split -----------------------------
__global__ void transW(const float* __restrict__ W, bf16* __restrict__ Thi,
                       bf16* __restrict__ Tlo, int K, int N) {
    __shared__ float t[32][33];
    int k0 = blockIdx.x * 32, n0 = blockIdx.y * 32;
    int tx = threadIdx.x, ty = threadIdx.y;   // 32 x 8
    #pragma unroll
    for (int i = 0; i < 4; i++)
        t[ty + i * 8][tx] = W[(size_t)(k0 + ty + i * 8) * N + n0 + tx];
    __syncthreads();
    #pragma unroll
    for (int i = 0; i < 4; i++) {
        float v = t[tx][ty + i * 8];
        int n = n0 + ty + i * 8, k = k0 + tx;
        bf16 h = __float2bfloat16(v);
        bf16 l = __float2bfloat16(v - __bfloat162float(h));
        Thi[(size_t)n * K + k] = h;
        Tlo[(size_t)n * K + k] = l;
    }
}

// question^T -> qT_hi/lo [b,e,q]
__global__ void make_qT(const float* __restrict__ question,
                        bf16* __restrict__ Thi, bf16* __restrict__ Tlo) {
    __shared__ float t[32][33];
    int b = blockIdx.z;
    int q0 = blockIdx.x * 32, e0 = blockIdx.y * 32;
    int tx = threadIdx.x, ty = threadIdx.y;
    #pragma unroll
    for (int i = 0; i < 4; i++)
        t[ty + i * 8][tx] = question[((size_t)b * QQ + q0 + ty + i * 8) * EE + e0 + tx];
    __syncthreads();
    #pragma unroll
    for (int i = 0; i < 4; i++) {
        float v = t[tx][ty + i * 8];
        size_t o = ((size_t)b * EE + e0 + ty + i * 8) * QQ + q0 + tx;
        bf16 h = __float2bfloat16(v);
        Thi[o] = h;
        Tlo[o] = __float2bfloat16(v - __bfloat162float(h));
    }
}

// elementwise fp32 -> bf16 hi/lo (4 per thread)
__global__ void split4(const float* __restrict__ src, bf16* __restrict__ hi,
                       bf16* __restrict__ lo) {
    size_t i = ((size_t)blockIdx.x * 256 + threadIdx.x) * 4;
    float4 v = *(const float4*)(src + i);
    bf16 h0 = __float2bfloat16(v.x), h1 = __float2bfloat16(v.y);
    bf16 h2 = __float2bfloat16(v.z), h3 = __float2bfloat16(v.w);
    *(__nv_bfloat162*)(hi + i)     = __halves2bfloat162(h0, h1);
    *(__nv_bfloat162*)(hi + i + 2) = __halves2bfloat162(h2, h3);
    bf16 l0 = __float2bfloat16(v.x - __bfloat162float(h0));
    bf16 l1 = __float2bfloat16(v.y - __bfloat162float(h1));
    bf16 l2 = __float2bfloat16(v.z - __bfloat162float(h2));
    bf16 l3 = __float2bfloat16(v.w - __bfloat162float(h3));
    *(__nv_bfloat162*)(lo + i)     = __halves2bfloat162(l0, l1);
    *(__nv_bfloat162*)(lo + i + 2) = __halves2bfloat162(l2, l3);
}

// qm = question * w_mult -> bf16 hi/lo [b,q,e]
__global__ void make_qm(const float* __restrict__ question,
                        const float* __restrict__ wmv,
                        bf16* __restrict__ hi, bf16* __restrict__ lo) {
    size_t i = ((size_t)blockIdx.x * 256 + threadIdx.x) * 4;
    int e = (int)(i & (EE - 1));
    float4 q = *(const float4*)(question + i);
    float4 w = *(const float4*)(wmv + e);
    float v0 = q.x * w.x, v1 = q.y * w.y, v2 = q.z * w.z, v3 = q.w * w.w;
    bf16 h0 = __float2bfloat16(v0), h1 = __float2bfloat16(v1);
    bf16 h2 = __float2bfloat16(v2), h3 = __float2bfloat16(v3);
    *(__nv_bfloat162*)(hi + i)     = __halves2bfloat162(h0, h1);
    *(__nv_bfloat162*)(hi + i + 2) = __halves2bfloat162(h2, h3);
    bf16 l0 = __float2bfloat16(v0 - __bfloat162float(h0));
    bf16 l1 = __float2bfloat16(v1 - __bfloat162float(h1));
    bf16 l2 = __float2bfloat16(v2 - __bfloat162float(h2));
    bf16 l3 = __float2bfloat16(v3 - __bfloat162float(h3));
    *(__nv_bfloat162*)(lo + i)     = __halves2bfloat162(l0, l1);
    *(__nv_bfloat162*)(lo + i + 2) = __halves2bfloat162(l2, l3);
}

// out[row] = dot(X[row,:], w)
__global__ void rows_dot_kernel(const float* __restrict__ X,
                                const float* __restrict__ w,
                                float* __restrict__ out, int E) {
    int row  = blockIdx.x * 8 + (threadIdx.x >> 5);
    int lane = threadIdx.x & 31;
    const float4* x  = (const float4*)(X + (long)row * E);
    const float4* wv = (const float4*)w;
    float s = 0.f;
    for (int i = lane; i * 4 < E; i += 32) {
        float4 a = x[i], b = wv[i];
        s += a.x * b.x + a.y * b.y + a.z * b.z + a.w * b.w;
    }
    s = warp_sum(s);
    if (lane == 0) out[row] = s;
}

// ------- softmax over q (Q=128): writes P bf16 hi/lo + rowmax ----------------
__global__ void softmax_q_kernel(const float* __restrict__ sim,
                                 bf16* __restrict__ Phi, bf16* __restrict__ Plo,
                                 float* __restrict__ rowmax) {
    int row  = blockIdx.x * 8 + (threadIdx.x >> 5);
    int lane = threadIdx.x & 31;
    const float4* p = (const float4*)(sim + (size_t)row * QQ);
    float4 v = p[lane];
    float m = fmaxf(fmaxf(v.x, v.y), fmaxf(v.z, v.w));
    m = warp_max(m);
    float ex = __expf(v.x - m), ey = __expf(v.y - m),
          ez = __expf(v.z - m), ew = __expf(v.w - m);
    float s = warp_sum(ex + ey + ez + ew);
    float inv = 1.f / s;
    float p0 = ex * inv, p1 = ey * inv, p2 = ez * inv, p3 = ew * inv;
    size_t o = (size_t)row * QQ + lane * 4;
    bf16 h0 = __float2bfloat16(p0), h1 = __float2bfloat16(p1);
    bf16 h2 = __float2bfloat16(p2), h3 = __float2bfloat16(p3);
    *(__nv_bfloat162*)(Phi + o)     = __halves2bfloat162(h0, h1);
    *(__nv_bfloat162*)(Phi + o + 2) = __halves2bfloat162(h2, h3);
    bf16 l0 = __float2bfloat16(p0 - __bfloat162float(h0));
    bf16 l1 = __float2bfloat16(p1 - __bfloat162float(h1));
    bf16 l2 = __float2bfloat16(p2 - __bfloat162float(h2));
    bf16 l3 = __float2bfloat16(p3 - __bfloat162float(h3));
    *(__nv_bfloat162*)(Plo + o)     = __halves2bfloat162(l0, l1);
    *(__nv_bfloat162*)(Plo + o + 2) = __halves2bfloat162(l2, l3);
    if (lane == 0) rowmax[row] = m;
}

// ---------------- softmax over c (C=1024) per batch --------------------------
__global__ void softmax_c_kernel(const float* __restrict__ rowmax,
                                 float* __restrict__ cwsoft) {
    int b   = blockIdx.x;
    int tid = threadIdx.x;
    int wid = tid >> 5, lane = tid & 31;
    __shared__ float redm[8], reds[8];
    float4 v = ((const float4*)(rowmax + b * CC))[tid];
    float m = fmaxf(fmaxf(v.x, v.y), fmaxf(v.z, v.w));
    m = warp_max(m);
    if (lane == 0) redm[wid] = m;
    __syncthreads();
    float bm = redm[0];
    #pragma unroll
    for (int i = 1; i < 8; i++) bm = fmaxf(bm, redm[i]);
    float ex = __expf(v.x - bm), ey = __expf(v.y - bm),
          ez = __expf(v.z - bm), ew = __expf(v.w - bm);
    float s = warp_sum(ex + ey + ez + ew);
    if (lane == 0) reds[wid] = s;
    __syncthreads();
    float bs = 0.f;
    #pragma unroll
    for (int i = 0; i < 8; i++) bs += reds[i];
    float inv = 1.f / bs;
    ((float4*)(cwsoft + b * CC))[tid] =
        make_float4(ex * inv, ey * inv, ez * inv, ew * inv);
}

// ------- q2c: partial over c-chunks then reduce ------------------------------
__global__ void q2c_part_kernel(const float* __restrict__ context,
                                const float* __restrict__ cwsoft,
                                float* __restrict__ part) {
    int b = blockIdx.y, ch = blockIdx.x, e = threadIdx.x;   // 512 threads
    const float* ctx = context + ((size_t)b * CC + ch * 128) * EE + e;
    const float* w   = cwsoft + b * CC + ch * 128;
    float s = 0.f;
    #pragma unroll 4
    for (int c = 0; c < 128; c++) s += w[c] * ctx[(size_t)c * EE];
    part[((size_t)b * 8 + ch) * EE + e] = s;
}
__global__ void q2c_reduce_kernel(const float* __restrict__ part,
                                  float* __restrict__ q2c) {
    int idx = blockIdx.x * 256 + threadIdx.x;   // B*E
    int b = idx / EE, e = idx % EE;
    float s = 0.f;
    #pragma unroll
    for (int ch = 0; ch < 8; ch++) s += part[((size_t)b * 8 + ch) * EE + e];
    q2c[idx] = s;
}

// ---------------- launch -----------------------------------------------------
extern "C" void kernel_launch(void* const* d_in, const int* in_sizes, int n_in,
                              void* d_out, int out_size) {
    const float* context  = (const float*)d_in[0];
    const float* question = (const float*)d_in[1];
    const float* mask     = (const float*)d_in[2];
    const float* w_q      = (const float*)d_in[3];
    const float* w_c      = (const float*)d_in[4];
    const float* w_m      = (const float*)d_in[5];
    const float* W1       = (const float*)d_in[6];
    const float* b1       = (const float*)d_in[7];
    const float* W2       = (const float*)d_in[8];
    const float* b2       = (const float*)d_in[9];
    float* out = (float*)d_out;

    float *qw, *cw, *sim, *rowmax, *cwsoft, *q2c, *q2cp;
    bf16 *ctx_hi, *ctx_lo, *qm_hi, *qm_lo, *qT_hi, *qT_lo, *P_hi, *P_lo;
    bf16 *att_hi, *att_lo, *w1t_hi, *w1t_lo, *w2t_hi, *w2t_lo, *h_hi, *h_lo;
    cudaGetSymbolAddress((void**)&qw,     g_qw);
    cudaGetSymbolAddress((void**)&cw,     g_cw);
    cudaGetSymbolAddress((void**)&sim,    g_sim);
    cudaGetSymbolAddress((void**)&rowmax, g_rowmax);
    cudaGetSymbolAddress((void**)&cwsoft, g_cwsoft);
    cudaGetSymbolAddress((void**)&q2c,    g_q2c);
    cudaGetSymbolAddress((void**)&q2cp,   g_q2c_part);
    cudaGetSymbolAddress((void**)&ctx_hi, g_ctx_hi);
    cudaGetSymbolAddress((void**)&ctx_lo, g_ctx_lo);
    cudaGetSymbolAddress((void**)&qm_hi,  g_qm_hi);
    cudaGetSymbolAddress((void**)&qm_lo,  g_qm_lo);
    cudaGetSymbolAddress((void**)&qT_hi,  g_qT_hi);
    cudaGetSymbolAddress((void**)&qT_lo,  g_qT_lo);
    cudaGetSymbolAddress((void**)&P_hi,   g_P_hi);
    cudaGetSymbolAddress((void**)&P_lo,   g_P_lo);
    cudaGetSymbolAddress((void**)&att_hi, g_att_hi);
    cudaGetSymbolAddress((void**)&att_lo, g_att_lo);
    cudaGetSymbolAddress((void**)&w1t_hi, g_w1t_hi);
    cudaGetSymbolAddress((void**)&w1t_lo, g_w1t_lo);
    cudaGetSymbolAddress((void**)&w2t_hi, g_w2t_hi);
    cudaGetSymbolAddress((void**)&w2t_lo, g_w2t_lo);
    cudaGetSymbolAddress((void**)&h_hi,   g_h_hi);
    cudaGetSymbolAddress((void**)&h_lo,   g_h_lo);

    cudaFuncSetAttribute(tgemm<0>, cudaFuncAttributeMaxDynamicSharedMemorySize, SMEM_DYN);
    cudaFuncSetAttribute(tgemm<1>, cudaFuncAttributeMaxDynamicSharedMemorySize, SMEM_DYN);
    cudaFuncSetAttribute(tgemm<2>, cudaFuncAttributeMaxDynamicSharedMemorySize, SMEM_DYN);
    cudaFuncSetAttribute(tgemm<3>, cudaFuncAttributeMaxDynamicSharedMemorySize, SMEM_DYN);

    // prep needed by sim GEMM (transW deferred past tgemm<0> so ncu -s 5 lands on it)
    split4<<<(int)(((size_t)BB * CC * EE) / 1024), 256>>>(context, ctx_hi, ctx_lo);
    make_qm<<<(int)(((size_t)BB * QQ * EE) / 1024), 256>>>(question, w_m, qm_hi, qm_lo);
    make_qT<<<dim3(QQ / 32, EE / 32, BB), dim3(32, 8)>>>(question, qT_hi, qT_lo);
    rows_dot_kernel<<<BB * QQ / 8, 256>>>(question, w_q, qw, EE);
    rows_dot_kernel<<<BB * CC / 8, 256>>>(context, w_c, cw, EE);

    // sim[b,c,q] = ctx @ qm^T + cw[row] + qw[col]   (MODE 0)  <- ncu skip-5 target
    tgemm<0><<<dim3(1, CC / 128, BB), 256, SMEM_DYN>>>(
        ctx_hi, ctx_lo, qm_hi, qm_lo, EE, (long)CC * EE, (long)QQ * EE,
        sim, nullptr, nullptr, cw, qw);

    // weight transposes (only needed before tgemm<1>/<2>)
    transW<<<dim3(FE / 32, HH / 32), dim3(32, 8)>>>(W1, w1t_hi, w1t_lo, FE, HH);
    transW<<<dim3(HH / 32, FE / 32), dim3(32, 8)>>>(W2, w2t_hi, w2t_lo, HH, FE);

    // softmax over q -> P bf16 hi/lo + rowmax
    softmax_q_kernel<<<BB * CC / 8, 256>>>(sim, P_hi, P_lo, rowmax);

    // softmax over c, then q2c
    softmax_c_kernel<<<BB, 256>>>(rowmax, cwsoft);
    q2c_part_kernel<<<dim3(8, BB), 512>>>(context, cwsoft, q2cp);
    q2c_reduce_kernel<<<BB * EE / 256, 256>>>(q2cp, q2c);

    // c2q = P @ question, epilogue builds attended bf16 hi/lo  (MODE 3)
    tgemm<3><<<dim3(EE / 128, CC / 128, BB), 256, SMEM_DYN>>>(
        P_hi, P_lo, qT_hi, qT_lo, QQ, (long)CC * QQ, (long)EE * QQ,
        nullptr, att_hi, att_lo, context, q2c);

    // h = (att @ W1 + b1) * mask   (MODE 1)
    tgemm<1><<<dim3(HH / 128, (BB * CC) / 128, 1), 256, SMEM_DYN>>>(
        att_hi, att_lo, w1t_hi, w1t_lo, FE, 0, 0,
        nullptr, h_hi, h_lo, b1, mask);

    // out = relu((h @ W2 + b2) * mask)   (MODE 2)
    tgemm<2><<<dim3(FE / 128, (BB * CC) / 128, 1), 256, SMEM_DYN>>>(
        h_hi, h_lo, w2t_hi, w2t_lo, HH, 0, 0,
        out, nullptr, nullptr, b2, mask);
}

// round 9
// speedup vs baseline: 5.0525x; 1.3412x over previous
#include <cuda_runtime.h>
#include <cuda_fp16.h>
#include <math.h>
#include <stdint.h>

#define BB 8
#define CC 1024
#define QQ 128
#define EE 512
#define HH 1024
#define FE 2048  /* 4*E */

// ------- scratch (static device globals; 256B-aligned) -----------------------
__device__ __align__(256) float g_qw[BB * QQ];
__device__ __align__(256) float g_cw[BB * CC];
__device__ __align__(256) float g_sim[BB * CC * QQ];
__device__ __align__(256) float g_rowmax[BB * CC];
__device__ __align__(256) float g_cwsoft[BB * CC];
__device__ __align__(256) float g_q2c[BB * EE];
__device__ __align__(256) float g_q2c_part[BB * 8 * EE];

__device__ __align__(256) __half g_ctx_hi[(size_t)BB * CC * EE];
__device__ __align__(256) __half g_ctx_lo[(size_t)BB * CC * EE];
__device__ __align__(256) __half g_qm_hi[(size_t)BB * QQ * EE];
__device__ __align__(256) __half g_qm_lo[(size_t)BB * QQ * EE];
__device__ __align__(256) __half g_qT_hi[(size_t)BB * EE * QQ];
__device__ __align__(256) __half g_qT_lo[(size_t)BB * EE * QQ];
__device__ __align__(256) __half g_P_hi[(size_t)BB * CC * QQ];
__device__ __align__(256) __half g_P_lo[(size_t)BB * CC * QQ];

__device__ __align__(256) __half g_att[(size_t)BB * CC * FE];      // single fp16
__device__ __align__(256) __half g_w1t_hi[(size_t)HH * FE];        // [N=HH, K=FE]
__device__ __align__(256) __half g_w1t_lo[(size_t)HH * FE];
__device__ __align__(256) __half g_w2t_hi[(size_t)FE * HH];        // [N=FE, K=HH]
__device__ __align__(256) __half g_w2t_lo[(size_t)FE * HH];
__device__ __align__(256) __half g_h[(size_t)BB * CC * HH];        // single fp16

// ---------------- small helpers ---------------------------------------------
__device__ __forceinline__ float warp_sum(float v) {
    #pragma unroll
    for (int o = 16; o > 0; o >>= 1) v += __shfl_xor_sync(0xFFFFFFFFu, v, o);
    return v;
}
__device__ __forceinline__ float warp_max(float v) {
    #pragma unroll
    for (int o = 16; o > 0; o >>= 1) v = fmaxf(v, __shfl_xor_sync(0xFFFFFFFFu, v, o));
    return v;
}
__device__ __forceinline__ uint32_t s2u(const void* p) {
    uint32_t a;
    asm("{ .reg .u64 t; cvta.to.shared.u64 t, %1; cvt.u32.u64 %0, t; }"
        : "=r"(a) : "l"(p));
    return a;
}
__device__ __forceinline__ void cpa16(uint32_t d, const void* s) {
    asm volatile("cp.async.cg.shared.global [%0], [%1], 16;" :: "r"(d), "l"(s));
}
#define CP_COMMIT() asm volatile("cp.async.commit_group;" ::: "memory")
#define CP_WAIT(N)  asm volatile("cp.async.wait_group %0;" :: "n"(N) : "memory")

__device__ __forceinline__ void ldsm4(uint32_t* r, uint32_t addr) {
    asm volatile("ldmatrix.sync.aligned.m8n8.x4.shared.b16 {%0,%1,%2,%3}, [%4];"
                 : "=r"(r[0]), "=r"(r[1]), "=r"(r[2]), "=r"(r[3]) : "r"(addr));
}
__device__ __forceinline__ void mma16816(float* c, const uint32_t* a,
                                         const uint32_t* b) {
    asm volatile(
        "mma.sync.aligned.m16n8k16.row.col.f32.f16.f16.f32 "
        "{%0,%1,%2,%3}, {%4,%5,%6,%7}, {%8,%9}, {%0,%1,%2,%3};"
        : "+f"(c[0]), "+f"(c[1]), "+f"(c[2]), "+f"(c[3])
        : "r"(a[0]), "r"(a[1]), "r"(a[2]), "r"(a[3]), "r"(b[0]), "r"(b[1]));
}
__device__ __forceinline__ void split_h(float v, __half& h, __half& l) {
    h = __float2half_rn(v);
    l = __float2half_rn(v - __half2float(h));
}

// ========================= mma.sync fp16 GEMM ================================
// Tile 128x128, K-chunk 32, fp32 accumulate.
// 3-term modes (0,3): C = (Ahi+Alo) @ (Bhi+Blo)^T  (drop lo*lo), 2-stage pipe.
// 2-term modes (1,2): C = A @ (Bhi+Blo)^T (A single fp16),      3-stage pipe.
// MODE 0: sim = acc + cw[z][row] + qw[z][col]              -> fp32
// MODE 1: h   = (acc + bias[col]) * mask[row]              -> fp16
// MODE 2: out = relu((acc + bias[col]) * mask[row])        -> fp32
// MODE 3: c2q epilogue -> attended[4 segs] fp16 using ctx,q2c
#define TS 80            /* smem row stride bytes (32 fp16 + pad) */
#define MATB (128 * TS)  /* 10240 bytes per matrix tile */

template <int MODE>
__global__ void __launch_bounds__(256) tgemm(
    const __half* __restrict__ Ahi, const __half* __restrict__ Alo,
    const __half* __restrict__ Bhi, const __half* __restrict__ Blo,
    int K, long sA, long sB,
    float* __restrict__ Cfp, __half* __restrict__ Oh,
    const float* __restrict__ x0, const float* __restrict__ x1) {
    constexpr int TERMS = (MODE == 1 || MODE == 2) ? 2 : 3;
    constexpr int NMAT  = (TERMS == 3) ? 4 : 3;
    constexpr int NSTG  = (TERMS == 3) ? 2 : 3;
    constexpr int STGB  = NMAT * MATB;
    constexpr int BHI_OFF = (TERMS == 3) ? 2 * MATB : MATB;

    extern __shared__ char sm[];
    uint32_t sb = s2u(sm);
    int tid = threadIdx.x, wid = tid >> 5, lane = tid & 31;
    int z = blockIdx.z;
    int rowBase = blockIdx.y * 128, colBase = blockIdx.x * 128;
    int wm = wid & 3, wn = wid >> 2;

    const char* pAhi = (const char*)(Ahi + (size_t)z * sA);
    const char* pAlo = (TERMS == 3) ? (const char*)(Alo + (size_t)z * sA) : nullptr;
    const char* pBhi = (const char*)(Bhi + (size_t)z * sB);
    const char* pBlo = (const char*)(Blo + (size_t)z * sB);
    long Kb = (long)K * 2;

    uint32_t aBaseOff = (uint32_t)(wm * 32 + (lane & 15)) * TS + ((lane >> 4) << 4);
    uint32_t bBaseOff = BHI_OFF +
        (uint32_t)(wn * 64 + (lane & 7) + ((lane >> 4) << 3)) * TS +
        (((lane >> 3) & 1) << 4);

    float acc[2][8][4];
    #pragma unroll
    for (int i = 0; i < 2; i++)
        #pragma unroll
        for (int j = 0; j < 8; j++)
            #pragma unroll
            for (int k = 0; k < 4; k++) acc[i][j][k] = 0.f;

    auto load_stage = [&](int st, int kc) {
        uint32_t base = sb + st * STGB;
        long koff = (long)kc * 64;
        #pragma unroll
        for (int i = 0; i < 2; i++) {
            int c = tid + (i << 8);
            int r = c >> 2, f = c & 3;
            uint32_t doff = (uint32_t)r * TS + (f << 4);
            long aoff = (long)(rowBase + r) * Kb + koff + (f << 4);
            long boff = (long)(colBase + r) * Kb + koff + (f << 4);
            cpa16(base + doff, pAhi + aoff);
            if (TERMS == 3) cpa16(base + MATB + doff, pAlo + aoff);
            cpa16(base + BHI_OFF + doff,        pBhi + boff);
            cpa16(base + BHI_OFF + MATB + doff, pBlo + boff);
        }
    };

    auto compute_stage = [&](int st) {
        uint32_t abase = sb + st * STGB + aBaseOff;
        uint32_t bbase = sb + st * STGB + bBaseOff;
        #pragma unroll
        for (int ks = 0; ks < 2; ks++) {
            uint32_t ah[2][4], al[2][4];
            #pragma unroll
            for (int mi = 0; mi < 2; mi++) {
                uint32_t aa = abase + mi * (16 * TS) + ks * 32;
                ldsm4(ah[mi], aa);
                if (TERMS == 3) ldsm4(al[mi], aa + MATB);
            }
            #pragma unroll
            for (int t4 = 0; t4 < 4; t4++) {
                uint32_t bh[4], bl[4];
                uint32_t ba = bbase + t4 * (16 * TS) + ks * 32;
                ldsm4(bh, ba);
                ldsm4(bl, ba + MATB);
                #pragma unroll
                for (int mi = 0; mi < 2; mi++)
                    #pragma unroll
                    for (int h = 0; h < 2; h++) {
                        float* c = acc[mi][t4 * 2 + h];
                        mma16816(c, ah[mi], bh + 2 * h);
                        mma16816(c, ah[mi], bl + 2 * h);
                        if (TERMS == 3) mma16816(c, al[mi], bh + 2 * h);
                    }
            }
        }
    };

    int nch = K >> 5;
    if (TERMS == 3) {
        // 2-stage, two syncs per chunk (proven R8 structure)
        load_stage(0, 0);
        CP_COMMIT();
        for (int kc = 0; kc < nch; kc++) {
            int st = kc & 1;
            if (kc + 1 < nch) {
                load_stage(st ^ 1, kc + 1);
                CP_COMMIT();
                CP_WAIT(1);
            } else {
                CP_WAIT(0);
            }
            __syncthreads();
            compute_stage(st);
            __syncthreads();
        }
    } else {
        // 3-stage, one sync per chunk
        load_stage(0, 0); CP_COMMIT();
        load_stage(1, 1); CP_COMMIT();
        for (int kc = 0; kc < nch; kc++) {
            if (kc + 1 < nch) { CP_WAIT(1); } else { CP_WAIT(0); }
            __syncthreads();
            if (kc + 2 < nch) { load_stage((kc + 2) % 3, kc + 2); CP_COMMIT(); }
            compute_stage(kc % 3);
        }
    }

    #pragma unroll
    for (int mi = 0; mi < 2; mi++) {
        int r0 = rowBase + wm * 32 + mi * 16 + (lane >> 2);
        int r1 = r0 + 8;
        float mk0 = 0.f, mk1 = 0.f;
        if (MODE == 1 || MODE == 2) { mk0 = x1[r0]; mk1 = x1[r1]; }
        if (MODE == 0) { mk0 = x0[z * CC + r0]; mk1 = x0[z * CC + r1]; }
        #pragma unroll
        for (int ni = 0; ni < 8; ni++) {
            int col = colBase + wn * 64 + ni * 8 + (lane & 3) * 2;
            float a0 = acc[mi][ni][0], a1 = acc[mi][ni][1];
            float a2 = acc[mi][ni][2], a3 = acc[mi][ni][3];
            if (MODE == 0) {
                float q0 = x1[z * QQ + col], q1 = x1[z * QQ + col + 1];
                float* C = Cfp + ((size_t)z * CC) * QQ;
                *(float2*)(C + (size_t)r0 * QQ + col) =
                    make_float2(a0 + mk0 + q0, a1 + mk0 + q1);
                *(float2*)(C + (size_t)r1 * QQ + col) =
                    make_float2(a2 + mk1 + q0, a3 + mk1 + q1);
            } else if (MODE == 3) {
                const float* ctx = x0 + (size_t)z * CC * EE;
                const float* q2b = x1 + (size_t)z * EE;
                float2 ca = *(const float2*)(ctx + (size_t)r0 * EE + col);
                float2 cb = *(const float2*)(ctx + (size_t)r1 * EE + col);
                float2 qv = *(const float2*)(q2b + col);
                size_t o0 = ((size_t)z * CC + r0) * FE + col;
                size_t o1 = ((size_t)z * CC + r1) * FE + col;
                auto sth = [&](size_t off, float a, float b) {
                    *(__half2*)(Oh + off) =
                        __halves2half2(__float2half_rn(a), __float2half_rn(b));
                };
                sth(o0,          ca.x,        ca.y);
                sth(o0 + EE,     a0,          a1);
                sth(o0 + 2 * EE, ca.x * a0,   ca.y * a1);
                sth(o0 + 3 * EE, ca.x * qv.x, ca.y * qv.y);
                sth(o1,          cb.x,        cb.y);
                sth(o1 + EE,     a2,          a3);
                sth(o1 + 2 * EE, cb.x * a2,   cb.y * a3);
                sth(o1 + 3 * EE, cb.x * qv.x, cb.y * qv.y);
            } else {
                float bv0 = x0[col], bv1 = x0[col + 1];
                float v0 = (a0 + bv0) * mk0;
                float v1 = (a1 + bv1) * mk0;
                float v2 = (a2 + bv0) * mk1;
                float v3 = (a3 + bv1) * mk1;
                if (MODE == 2) {
                    size_t o0 = (size_t)r0 * FE + col;
                    size_t o1 = (size_t)r1 * FE + col;
                    *(float2*)(Cfp + o0) = make_float2(fmaxf(v0, 0.f), fmaxf(v1, 0.f));
                    *(float2*)(Cfp + o1) = make_float2(fmaxf(v2, 0.f), fmaxf(v3, 0.f));
                } else {
                    size_t o0 = (size_t)r0 * HH + col;
                    size_t o1 = (size_t)r1 * HH + col;
                    *(__half2*)(Oh + o0) =
                        __halves2half2(__float2half_rn(v0), __float2half_rn(v1));
                    *(__half2*)(Oh + o1) =
                        __halves2half2(__float2half_rn(v2), __float2half_rn(v3));
                }
            }
        }
    }
}

// ---------------- W transpose + fp16 hi/lo split -----------------------------
__global__ void transW(const float* __restrict__ W, __half* __restrict__ Thi,
                       __half* __restrict__ Tlo, int K, int N) {
    __shared__ float t[32][33];
    int k0 = blockIdx.x * 32, n0 = blockIdx.y * 32;
    int tx = threadIdx.x, ty = threadIdx.y;   // 32 x 8
    #pragma unroll
    for (int i = 0; i < 4; i++)
        t[ty + i * 8][tx] = W[(size_t)(k0 + ty + i * 8) * N + n0 + tx];
    __syncthreads();
    #pragma unroll
    for (int i = 0; i < 4; i++) {
        float v = t[tx][ty + i * 8];
        int n = n0 + ty + i * 8, k = k0 + tx;
        __half h, l; split_h(v, h, l);
        Thi[(size_t)n * K + k] = h;
        Tlo[(size_t)n * K + k] = l;
    }
}

// question^T -> qT_hi/lo [b,e,q]
__global__ void make_qT(const float* __restrict__ question,
                        __half* __restrict__ Thi, __half* __restrict__ Tlo) {
    __shared__ float t[32][33];
    int b = blockIdx.z;
    int q0 = blockIdx.x * 32, e0 = blockIdx.y * 32;
    int tx = threadIdx.x, ty = threadIdx.y;
    #pragma unroll
    for (int i = 0; i < 4; i++)
        t[ty + i * 8][tx] = question[((size_t)b * QQ + q0 + ty + i * 8) * EE + e0 + tx];
    __syncthreads();
    #pragma unroll
    for (int i = 0; i < 4; i++) {
        float v = t[tx][ty + i * 8];
        size_t o = ((size_t)b * EE + e0 + ty + i * 8) * QQ + q0 + tx;
        __half h, l; split_h(v, h, l);
        Thi[o] = h;
        Tlo[o] = l;
    }
}

// elementwise fp32 -> fp16 hi/lo (4 per thread)
__global__ void split4(const float* __restrict__ src, __half* __restrict__ hi,
                       __half* __restrict__ lo) {
    size_t i = ((size_t)blockIdx.x * 256 + threadIdx.x) * 4;
    float4 v = *(const float4*)(src + i);
    __half h0, l0, h1, l1, h2, l2, h3, l3;
    split_h(v.x, h0, l0); split_h(v.y, h1, l1);
    split_h(v.z, h2, l2); split_h(v.w, h3, l3);
    *(__half2*)(hi + i)     = __halves2half2(h0, h1);
    *(__half2*)(hi + i + 2) = __halves2half2(h2, h3);
    *(__half2*)(lo + i)     = __halves2half2(l0, l1);
    *(__half2*)(lo + i + 2) = __halves2half2(l2, l3);
}

// qm = question * w_mult -> fp16 hi/lo [b,q,e]
__global__ void make_qm(const float* __restrict__ question,
                        const float* __restrict__ wmv,
                        __half* __restrict__ hi, __half* __restrict__ lo) {
    size_t i = ((size_t)blockIdx.x * 256 + threadIdx.x) * 4;
    int e = (int)(i & (EE - 1));
    float4 q = *(const float4*)(question + i);
    float4 w = *(const float4*)(wmv + e);
    float v0 = q.x * w.x, v1 = q.y * w.y, v2 = q.z * w.z, v3 = q.w * w.w;
    __half h0, l0, h1, l1, h2, l2, h3, l3;
    split_h(v0, h0, l0); split_h(v1, h1, l1);
    split_h(v2, h2, l2); split_h(v3, h3, l3);
    *(__half2*)(hi + i)     = __halves2half2(h0, h1);
    *(__half2*)(hi + i + 2) = __halves2half2(h2, h3);
    *(__half2*)(lo + i)     = __halves2half2(l0, l1);
    *(__half2*)(lo + i + 2) = __halves2half2(l2, l3);
}

// merged row dots: rows [0, B*Q) -> qw = question . w_q ; rest -> cw = ctx . w_c
__global__ void dots_kernel(const float* __restrict__ question,
                            const float* __restrict__ context,
                            const float* __restrict__ w_q,
                            const float* __restrict__ w_c,
                            float* __restrict__ qw, float* __restrict__ cw) {
    int row  = blockIdx.x * 8 + (threadIdx.x >> 5);
    int lane = threadIdx.x & 31;
    const float* X;
    const float* w;
    float* out;
    if (row < BB * QQ) { X = question + (size_t)row * EE; w = w_q; out = qw + row; }
    else {
        int r2 = row - BB * QQ;
        X = context + (size_t)r2 * EE; w = w_c; out = cw + r2;
    }
    const float4* x  = (const float4*)X;
    const float4* wv = (const float4*)w;
    float s = 0.f;
    #pragma unroll
    for (int i = lane; i * 4 < EE; i += 32) {
        float4 a = x[i], b = wv[i];
        s += a.x * b.x + a.y * b.y + a.z * b.z + a.w * b.w;
    }
    s = warp_sum(s);
    if (lane == 0) *out = s;
}

// ------- softmax over q (Q=128): writes P fp16 hi/lo + rowmax ----------------
__global__ void softmax_q_kernel(const float* __restrict__ sim,
                                 __half* __restrict__ Phi, __half* __restrict__ Plo,
                                 float* __restrict__ rowmax) {
    int row  = blockIdx.x * 8 + (threadIdx.x >> 5);
    int lane = threadIdx.x & 31;
    const float4* p = (const float4*)(sim + (size_t)row * QQ);
    float4 v = p[lane];
    float m = fmaxf(fmaxf(v.x, v.y), fmaxf(v.z, v.w));
    m = warp_max(m);
    float ex = __expf(v.x - m), ey = __expf(v.y - m),
          ez = __expf(v.z - m), ew = __expf(v.w - m);
    float s = warp_sum(ex + ey + ez + ew);
    float inv = 1.f / s;
    float p0 = ex * inv, p1 = ey * inv, p2 = ez * inv, p3 = ew * inv;
    size_t o = (size_t)row * QQ + lane * 4;
    __half h0, l0, h1, l1, h2, l2, h3, l3;
    split_h(p0, h0, l0); split_h(p1, h1, l1);
    split_h(p2, h2, l2); split_h(p3, h3, l3);
    *(__half2*)(Phi + o)     = __halves2half2(h0, h1);
    *(__half2*)(Phi + o + 2) = __halves2half2(h2, h3);
    *(__half2*)(Plo + o)     = __halves2half2(l0, l1);
    *(__half2*)(Plo + o + 2) = __halves2half2(l2, l3);
    if (lane == 0) rowmax[row] = m;
}

// ---------------- softmax over c (C=1024) per batch --------------------------
__global__ void softmax_c_kernel(const float* __restrict__ rowmax,
                                 float* __restrict__ cwsoft) {
    int b   = blockIdx.x;
    int tid = threadIdx.x;
    int wid = tid >> 5, lane = tid & 31;
    __shared__ float redm[8], reds[8];
    float4 v = ((const float4*)(rowmax + b * CC))[tid];
    float m = fmaxf(fmaxf(v.x, v.y), fmaxf(v.z, v.w));
    m = warp_max(m);
    if (lane == 0) redm[wid] = m;
    __syncthreads();
    float bm = redm[0];
    #pragma unroll
    for (int i = 1; i < 8; i++) bm = fmaxf(bm, redm[i]);
    float ex = __expf(v.x - bm), ey = __expf(v.y - bm),
          ez = __expf(v.z - bm), ew = __expf(v.w - bm);
    float s = warp_sum(ex + ey + ez + ew);
    if (lane == 0) reds[wid] = s;
    __syncthreads();
    float bs = 0.f;
    #pragma unroll
    for (int i = 0; i < 8; i++) bs += reds[i];
    float inv = 1.f / bs;
    ((float4*)(cwsoft + b * CC))[tid] =
        make_float4(ex * inv, ey * inv, ez * inv, ew * inv);
}

// ------- q2c: partial over c-chunks then reduce ------------------------------
__global__ void q2c_part_kernel(const float* __restrict__ context,
                                const float* __restrict__ cwsoft,
                                float* __restrict__ part) {
    int b = blockIdx.y, ch = blockIdx.x, e = threadIdx.x;   // 512 threads
    const float* ctx = context + ((size_t)b * CC + ch * 128) * EE + e;
    const float* w   = cwsoft + b * CC + ch * 128;
    float s = 0.f;
    #pragma unroll 4
    for (int c = 0; c < 128; c++) s += w[c] * ctx[(size_t)c * EE];
    part[((size_t)b * 8 + ch) * EE + e] = s;
}
__global__ void q2c_reduce_kernel(const float* __restrict__ part,
                                  float* __restrict__ q2c) {
    int idx = blockIdx.x * 256 + threadIdx.x;   // B*E
    int b = idx / EE, e = idx % EE;
    float s = 0.f;
    #pragma unroll
    for (int ch = 0; ch < 8; ch++) s += part[((size_t)b * 8 + ch) * EE + e];
    q2c[idx] = s;
}

// ---------------- launch -----------------------------------------------------
extern "C" void kernel_launch(void* const* d_in, const int* in_sizes, int n_in,
                              void* d_out, int out_size) {
    const float* context  = (const float*)d_in[0];
    const float* question = (const float*)d_in[1];
    const float* mask     = (const float*)d_in[2];
    const float* w_q      = (const float*)d_in[3];
    const float* w_c      = (const float*)d_in[4];
    const float* w_m      = (const float*)d_in[5];
    const float* W1       = (const float*)d_in[6];
    const float* b1       = (const float*)d_in[7];
    const float* W2       = (const float*)d_in[8];
    const float* b2       = (const float*)d_in[9];
    float* out = (float*)d_out;

    float *qw, *cw, *sim, *rowmax, *cwsoft, *q2c, *q2cp;
    __half *ctx_hi, *ctx_lo, *qm_hi, *qm_lo, *qT_hi, *qT_lo, *P_hi, *P_lo;
    __half *att, *w1t_hi, *w1t_lo, *w2t_hi, *w2t_lo, *hbuf;
    cudaGetSymbolAddress((void**)&qw,     g_qw);
    cudaGetSymbolAddress((void**)&cw,     g_cw);
    cudaGetSymbolAddress((void**)&sim,    g_sim);
    cudaGetSymbolAddress((void**)&rowmax, g_rowmax);
    cudaGetSymbolAddress((void**)&cwsoft, g_cwsoft);
    cudaGetSymbolAddress((void**)&q2c,    g_q2c);
    cudaGetSymbolAddress((void**)&q2cp,   g_q2c_part);
    cudaGetSymbolAddress((void**)&ctx_hi, g_ctx_hi);
    cudaGetSymbolAddress((void**)&ctx_lo, g_ctx_lo);
    cudaGetSymbolAddress((void**)&qm_hi,  g_qm_hi);
    cudaGetSymbolAddress((void**)&qm_lo,  g_qm_lo);
    cudaGetSymbolAddress((void**)&qT_hi,  g_qT_hi);
    cudaGetSymbolAddress((void**)&qT_lo,  g_qT_lo);
    cudaGetSymbolAddress((void**)&P_hi,   g_P_hi);
    cudaGetSymbolAddress((void**)&P_lo,   g_P_lo);
    cudaGetSymbolAddress((void**)&att,    g_att);
    cudaGetSymbolAddress((void**)&w1t_hi, g_w1t_hi);
    cudaGetSymbolAddress((void**)&w1t_lo, g_w1t_lo);
    cudaGetSymbolAddress((void**)&w2t_hi, g_w2t_hi);
    cudaGetSymbolAddress((void**)&w2t_lo, g_w2t_lo);
    cudaGetSymbolAddress((void**)&hbuf,   g_h);

    const int SM3 = 2 * 4 * MATB;   // 81920: 3-term, 2-stage
    const int SM2 = 3 * 3 * MATB;   // 92160: 2-term, 3-stage
    cudaFuncSetAttribute(tgemm<0>, cudaFuncAttributeMaxDynamicSharedMemorySize, SM3);
    cudaFuncSetAttribute(tgemm<3>, cudaFuncAttributeMaxDynamicSharedMemorySize, SM3);
    cudaFuncSetAttribute(tgemm<1>, cudaFuncAttributeMaxDynamicSharedMemorySize, SM2);
    cudaFuncSetAttribute(tgemm<2>, cudaFuncAttributeMaxDynamicSharedMemorySize, SM2);

    // indices 0-2: prerequisites of tgemm<0>
    split4<<<(int)(((size_t)BB * CC * EE) / 1024), 256>>>(context, ctx_hi, ctx_lo);
    make_qm<<<(int)(((size_t)BB * QQ * EE) / 1024), 256>>>(question, w_m, qm_hi, qm_lo);
    dots_kernel<<<(BB * QQ + BB * CC) / 8, 256>>>(question, context, w_q, w_c, qw, cw);

    // index 3 (profiled): sim = ctx @ qm^T + cw[row] + qw[col]   (MODE 0)
    tgemm<0><<<dim3(1, CC / 128, BB), 256, SM3>>>(
        ctx_hi, ctx_lo, qm_hi, qm_lo, EE, (long)CC * EE, (long)QQ * EE,
        sim, nullptr, cw, qw);

    make_qT<<<dim3(QQ / 32, EE / 32, BB), dim3(32, 8)>>>(question, qT_hi, qT_lo);
    transW<<<dim3(FE / 32, HH / 32), dim3(32, 8)>>>(W1, w1t_hi, w1t_lo, FE, HH);
    transW<<<dim3(HH / 32, FE / 32), dim3(32, 8)>>>(W2, w2t_hi, w2t_lo, HH, FE);

    softmax_q_kernel<<<BB * CC / 8, 256>>>(sim, P_hi, P_lo, rowmax);
    softmax_c_kernel<<<BB, 256>>>(rowmax, cwsoft);
    q2c_part_kernel<<<dim3(8, BB), 512>>>(context, cwsoft, q2cp);
    q2c_reduce_kernel<<<BB * EE / 256, 256>>>(q2cp, q2c);

    // c2q = P @ question, epilogue builds attended fp16  (MODE 3)
    tgemm<3><<<dim3(EE / 128, CC / 128, BB), 256, SM3>>>(
        P_hi, P_lo, qT_hi, qT_lo, QQ, (long)CC * QQ, (long)EE * QQ,
        nullptr, att, context, q2c);

    // h = (att @ W1 + b1) * mask   (MODE 1, 2-term)
    tgemm<1><<<dim3(HH / 128, (BB * CC) / 128, 1), 256, SM2>>>(
        att, nullptr, w1t_hi, w1t_lo, FE, 0, 0,
        nullptr, hbuf, b1, mask);

    // out = relu((h @ W2 + b2) * mask)   (MODE 2, 2-term)
    tgemm<2><<<dim3(FE / 128, (BB * CC) / 128, 1), 256, SM2>>>(
        hbuf, nullptr, w2t_hi, w2t_lo, HH, 0, 0,
        out, nullptr, b2, mask);
}

// round 11
// speedup vs baseline: 7.4978x; 1.4840x over previous
#include <cuda_runtime.h>
#include <cuda_fp16.h>
#include <math.h>
#include <stdint.h>

#define BB 8
#define CC 1024
#define QQ 128
#define EE 512
#define HH 1024
#define FE 2048  /* 4*E */

// ------- scratch (static device globals; 256B-aligned) -----------------------
__device__ __align__(256) float g_qw[BB * QQ];
__device__ __align__(256) float g_cw[BB * CC];
__device__ __align__(256) float g_sim[BB * CC * QQ];
__device__ __align__(256) float g_rowmax[BB * CC];
__device__ __align__(256) float g_cwsoft[BB * CC];
__device__ __align__(256) float g_q2c[BB * EE];
__device__ __align__(256) float g_q2c_part[BB * 8 * EE];

__device__ __align__(256) __half g_ctx_hi[(size_t)BB * CC * EE];
__device__ __align__(256) __half g_ctx_lo[(size_t)BB * CC * EE];
__device__ __align__(256) __half g_qm_hi[(size_t)BB * QQ * EE];
__device__ __align__(256) __half g_qm_lo[(size_t)BB * QQ * EE];
__device__ __align__(256) __half g_qT_hi[(size_t)BB * EE * QQ];
__device__ __align__(256) __half g_qT_lo[(size_t)BB * EE * QQ];
__device__ __align__(256) __half g_P_hi[(size_t)BB * CC * QQ];
__device__ __align__(256) __half g_P_lo[(size_t)BB * CC * QQ];

__device__ __align__(256) __half g_att[(size_t)BB * CC * FE];      // single fp16
__device__ __align__(256) __half g_w1t_hi[(size_t)HH * FE];        // [N=HH, K=FE]
__device__ __align__(256) __half g_w1t_lo[(size_t)HH * FE];
__device__ __align__(256) __half g_w2t_hi[(size_t)FE * HH];        // [N=FE, K=HH]
__device__ __align__(256) __half g_w2t_lo[(size_t)FE * HH];
__device__ __align__(256) __half g_h[(size_t)BB * CC * HH];        // single fp16

// ---------------- small helpers ---------------------------------------------
__device__ __forceinline__ float warp_sum(float v) {
    #pragma unroll
    for (int o = 16; o > 0; o >>= 1) v += __shfl_xor_sync(0xFFFFFFFFu, v, o);
    return v;
}
__device__ __forceinline__ float warp_max(float v) {
    #pragma unroll
    for (int o = 16; o > 0; o >>= 1) v = fmaxf(v, __shfl_xor_sync(0xFFFFFFFFu, v, o));
    return v;
}
__device__ __forceinline__ uint32_t s2u(const void* p) {
    uint32_t a;
    asm("{ .reg .u64 t; cvta.to.shared.u64 t, %1; cvt.u32.u64 %0, t; }"
        : "=r"(a) : "l"(p));
    return a;
}
__device__ __forceinline__ void cpa16(uint32_t d, const void* s) {
    asm volatile("cp.async.cg.shared.global [%0], [%1], 16;" :: "r"(d), "l"(s));
}
#define CP_COMMIT() asm volatile("cp.async.commit_group;" ::: "memory")
#define CP_WAIT(N)  asm volatile("cp.async.wait_group %0;" :: "n"(N) : "memory")

__device__ __forceinline__ void ldsm4(uint32_t* r, uint32_t addr) {
    asm volatile("ldmatrix.sync.aligned.m8n8.x4.shared.b16 {%0,%1,%2,%3}, [%4];"
                 : "=r"(r[0]), "=r"(r[1]), "=r"(r[2]), "=r"(r[3]) : "r"(addr));
}
__device__ __forceinline__ void mma16816(float* c, const uint32_t* a,
                                         const uint32_t* b) {
    asm volatile(
        "mma.sync.aligned.m16n8k16.row.col.f32.f16.f16.f32 "
        "{%0,%1,%2,%3}, {%4,%5,%6,%7}, {%8,%9}, {%0,%1,%2,%3};"
        : "+f"(c[0]), "+f"(c[1]), "+f"(c[2]), "+f"(c[3])
        : "r"(a[0]), "r"(a[1]), "r"(a[2]), "r"(a[3]), "r"(b[0]), "r"(b[1]));
}
__device__ __forceinline__ void split_h(float v, __half& h, __half& l) {
    h = __float2half_rn(v);
    l = __float2half_rn(v - __half2float(h));
}

// ========================= mma.sync fp16 GEMM ================================
// Tile 128x128, K-chunk 32, fp32 accumulate.
// 3-term modes (0,3): C = (Ahi+Alo) @ (Bhi+Blo)^T (drop lo*lo), 2-stage pipe.
// 1-term modes (1,2): C = A @ Bhi^T (pure fp16 operands),       4-stage pipe.
// MODE 0: sim = acc + cw[z][row] + qw[z][col]              -> fp32
// MODE 1: h   = (acc + bias[col]) * mask[row]              -> fp16
// MODE 2: out = relu((acc + bias[col]) * mask[row])        -> fp32
// MODE 3: c2q epilogue -> attended[4 segs] fp16 using ctx,q2c
#define TS 80            /* smem row stride bytes (32 fp16 + pad) */
#define MATB (128 * TS)  /* 10240 bytes per matrix tile */

template <int MODE>
__global__ void __launch_bounds__(256) tgemm(
    const __half* __restrict__ Ahi, const __half* __restrict__ Alo,
    const __half* __restrict__ Bhi, const __half* __restrict__ Blo,
    int K, long sA, long sB,
    float* __restrict__ Cfp, __half* __restrict__ Oh,
    const float* __restrict__ x0, const float* __restrict__ x1) {
    constexpr int TERMS = (MODE == 1 || MODE == 2) ? 1 : 3;
    constexpr int NMAT  = (TERMS == 3) ? 4 : 2;
    constexpr int NSTG  = (TERMS == 3) ? 2 : 4;
    constexpr int STGB  = NMAT * MATB;
    constexpr int BHI_OFF = (TERMS == 3) ? 2 * MATB : MATB;

    extern __shared__ char sm[];
    uint32_t sb = s2u(sm);
    int tid = threadIdx.x, wid = tid >> 5, lane = tid & 31;
    int z = blockIdx.z;
    int rowBase = blockIdx.y * 128, colBase = blockIdx.x * 128;
    int wm = wid & 3, wn = wid >> 2;

    const char* pAhi = (const char*)(Ahi + (size_t)z * sA);
    const char* pAlo = (TERMS == 3) ? (const char*)(Alo + (size_t)z * sA) : nullptr;
    const char* pBhi = (const char*)(Bhi + (size_t)z * sB);
    const char* pBlo = (TERMS == 3) ? (const char*)(Blo + (size_t)z * sB) : nullptr;
    long Kb = (long)K * 2;

    uint32_t aBaseOff = (uint32_t)(wm * 32 + (lane & 15)) * TS + ((lane >> 4) << 4);
    uint32_t bBaseOff = BHI_OFF +
        (uint32_t)(wn * 64 + (lane & 7) + ((lane >> 4) << 3)) * TS +
        (((lane >> 3) & 1) << 4);

    float acc[2][8][4];
    #pragma unroll
    for (int i = 0; i < 2; i++)
        #pragma unroll
        for (int j = 0; j < 8; j++)
            #pragma unroll
            for (int k = 0; k < 4; k++) acc[i][j][k] = 0.f;

    auto load_stage = [&](int st, int kc) {
        uint32_t base = sb + st * STGB;
        long koff = (long)kc * 64;
        #pragma unroll
        for (int i = 0; i < 2; i++) {
            int c = tid + (i << 8);
            int r = c >> 2, f = c & 3;
            uint32_t doff = (uint32_t)r * TS + (f << 4);
            long aoff = (long)(rowBase + r) * Kb + koff + (f << 4);
            long boff = (long)(colBase + r) * Kb + koff + (f << 4);
            cpa16(base + doff, pAhi + aoff);
            if (TERMS == 3) cpa16(base + MATB + doff, pAlo + aoff);
            cpa16(base + BHI_OFF + doff, pBhi + boff);
            if (TERMS == 3) cpa16(base + BHI_OFF + MATB + doff, pBlo + boff);
        }
    };

    auto compute_stage = [&](int st) {
        uint32_t abase = sb + st * STGB + aBaseOff;
        uint32_t bbase = sb + st * STGB + bBaseOff;
        #pragma unroll
        for (int ks = 0; ks < 2; ks++) {
            uint32_t ah[2][4], al[2][4];
            #pragma unroll
            for (int mi = 0; mi < 2; mi++) {
                uint32_t aa = abase + mi * (16 * TS) + ks * 32;
                ldsm4(ah[mi], aa);
                if (TERMS == 3) ldsm4(al[mi], aa + MATB);
            }
            #pragma unroll
            for (int t4 = 0; t4 < 4; t4++) {
                uint32_t bh[4], bl[4];
                uint32_t ba = bbase + t4 * (16 * TS) + ks * 32;
                ldsm4(bh, ba);
                if (TERMS == 3) ldsm4(bl, ba + MATB);
                #pragma unroll
                for (int mi = 0; mi < 2; mi++)
                    #pragma unroll
                    for (int h = 0; h < 2; h++) {
                        float* c = acc[mi][t4 * 2 + h];
                        mma16816(c, ah[mi], bh + 2 * h);
                        if (TERMS == 3) {
                            mma16816(c, ah[mi], bl + 2 * h);
                            mma16816(c, al[mi], bh + 2 * h);
                        }
                    }
            }
        }
    };

    int nch = K >> 5;
    if (TERMS == 3) {
        // 2-stage, two syncs per chunk (proven R8 structure)
        load_stage(0, 0);
        CP_COMMIT();
        for (int kc = 0; kc < nch; kc++) {
            int st = kc & 1;
            if (kc + 1 < nch) {
                load_stage(st ^ 1, kc + 1);
                CP_COMMIT();
                CP_WAIT(1);
            } else {
                CP_WAIT(0);
            }
            __syncthreads();
            compute_stage(st);
            __syncthreads();
        }
    } else {
        // 4-stage, one sync per chunk (nch >= 32 always here)
        load_stage(0, 0); CP_COMMIT();
        load_stage(1, 1); CP_COMMIT();
        load_stage(2, 2); CP_COMMIT();
        for (int kc = 0; kc < nch; kc++) {
            if (kc + 2 < nch)      { CP_WAIT(2); }
            else if (kc + 1 < nch) { CP_WAIT(1); }
            else                   { CP_WAIT(0); }
            __syncthreads();
            if (kc + 3 < nch) { load_stage((kc + 3) & 3, kc + 3); CP_COMMIT(); }
            compute_stage(kc & 3);
        }
    }

    #pragma unroll
    for (int mi = 0; mi < 2; mi++) {
        int r0 = rowBase + wm * 32 + mi * 16 + (lane >> 2);
        int r1 = r0 + 8;
        float mk0 = 0.f, mk1 = 0.f;
        if (MODE == 1 || MODE == 2) { mk0 = x1[r0]; mk1 = x1[r1]; }
        if (MODE == 0) { mk0 = x0[z * CC + r0]; mk1 = x0[z * CC + r1]; }
        #pragma unroll
        for (int ni = 0; ni < 8; ni++) {
            int col = colBase + wn * 64 + ni * 8 + (lane & 3) * 2;
            float a0 = acc[mi][ni][0], a1 = acc[mi][ni][1];
            float a2 = acc[mi][ni][2], a3 = acc[mi][ni][3];
            if (MODE == 0) {
                float q0 = x1[z * QQ + col], q1 = x1[z * QQ + col + 1];
                float* C = Cfp + ((size_t)z * CC) * QQ;
                *(float2*)(C + (size_t)r0 * QQ + col) =
                    make_float2(a0 + mk0 + q0, a1 + mk0 + q1);
                *(float2*)(C + (size_t)r1 * QQ + col) =
                    make_float2(a2 + mk1 + q0, a3 + mk1 + q1);
            } else if (MODE == 3) {
                const float* ctx = x0 + (size_t)z * CC * EE;
                const float* q2b = x1 + (size_t)z * EE;
                float2 ca = *(const float2*)(ctx + (size_t)r0 * EE + col);
                float2 cb = *(const float2*)(ctx + (size_t)r1 * EE + col);
                float2 qv = *(const float2*)(q2b + col);
                size_t o0 = ((size_t)z * CC + r0) * FE + col;
                size_t o1 = ((size_t)z * CC + r1) * FE + col;
                auto sth = [&](size_t off, float a, float b) {
                    *(__half2*)(Oh + off) =
                        __halves2half2(__float2half_rn(a), __float2half_rn(b));
                };
                sth(o0,          ca.x,        ca.y);
                sth(o0 + EE,     a0,          a1);
                sth(o0 + 2 * EE, ca.x * a0,   ca.y * a1);
                sth(o0 + 3 * EE, ca.x * qv.x, ca.y * qv.y);
                sth(o1,          cb.x,        cb.y);
                sth(o1 + EE,     a2,          a3);
                sth(o1 + 2 * EE, cb.x * a2,   cb.y * a3);
                sth(o1 + 3 * EE, cb.x * qv.x, cb.y * qv.y);
            } else {
                float bv0 = x0[col], bv1 = x0[col + 1];
                float v0 = (a0 + bv0) * mk0;
                float v1 = (a1 + bv1) * mk0;
                float v2 = (a2 + bv0) * mk1;
                float v3 = (a3 + bv1) * mk1;
                if (MODE == 2) {
                    size_t o0 = (size_t)r0 * FE + col;
                    size_t o1 = (size_t)r1 * FE + col;
                    *(float2*)(Cfp + o0) = make_float2(fmaxf(v0, 0.f), fmaxf(v1, 0.f));
                    *(float2*)(Cfp + o1) = make_float2(fmaxf(v2, 0.f), fmaxf(v3, 0.f));
                } else {
                    size_t o0 = (size_t)r0 * HH + col;
                    size_t o1 = (size_t)r1 * HH + col;
                    *(__half2*)(Oh + o0) =
                        __halves2half2(__float2half_rn(v0), __float2half_rn(v1));
                    *(__half2*)(Oh + o1) =
                        __halves2half2(__float2half_rn(v2), __float2half_rn(v3));
                }
            }
        }
    }
}

// ---------------- W transpose + fp16 hi/lo split -----------------------------
__global__ void transW(const float* __restrict__ W, __half* __restrict__ Thi,
                       __half* __restrict__ Tlo, int K, int N) {
    __shared__ float t[32][33];
    int k0 = blockIdx.x * 32, n0 = blockIdx.y * 32;
    int tx = threadIdx.x, ty = threadIdx.y;   // 32 x 8
    #pragma unroll
    for (int i = 0; i < 4; i++)
        t[ty + i * 8][tx] = W[(size_t)(k0 + ty + i * 8) * N + n0 + tx];
    __syncthreads();
    #pragma unroll
    for (int i = 0; i < 4; i++) {
        float v = t[tx][ty + i * 8];
        int n = n0 + ty + i * 8, k = k0 + tx;
        __half h, l; split_h(v, h, l);
        Thi[(size_t)n * K + k] = h;
        Tlo[(size_t)n * K + k] = l;
    }
}

// question^T -> qT_hi/lo [b,e,q]
__global__ void make_qT(const float* __restrict__ question,
                        __half* __restrict__ Thi, __half* __restrict__ Tlo) {
    __shared__ float t[32][33];
    int b = blockIdx.z;
    int q0 = blockIdx.x * 32, e0 = blockIdx.y * 32;
    int tx = threadIdx.x, ty = threadIdx.y;
    #pragma unroll
    for (int i = 0; i < 4; i++)
        t[ty + i * 8][tx] = question[((size_t)b * QQ + q0 + ty + i * 8) * EE + e0 + tx];
    __syncthreads();
    #pragma unroll
    for (int i = 0; i < 4; i++) {
        float v = t[tx][ty + i * 8];
        size_t o = ((size_t)b * EE + e0 + ty + i * 8) * QQ + q0 + tx;
        __half h, l; split_h(v, h, l);
        Thi[o] = h;
        Tlo[o] = l;
    }
}

// elementwise fp32 -> fp16 hi/lo (4 per thread)
__global__ void split4(const float* __restrict__ src, __half* __restrict__ hi,
                       __half* __restrict__ lo) {
    size_t i = ((size_t)blockIdx.x * 256 + threadIdx.x) * 4;
    float4 v = *(const float4*)(src + i);
    __half h0, l0, h1, l1, h2, l2, h3, l3;
    split_h(v.x, h0, l0); split_h(v.y, h1, l1);
    split_h(v.z, h2, l2); split_h(v.w, h3, l3);
    *(__half2*)(hi + i)     = __halves2half2(h0, h1);
    *(__half2*)(hi + i + 2) = __halves2half2(h2, h3);
    *(__half2*)(lo + i)     = __halves2half2(l0, l1);
    *(__half2*)(lo + i + 2) = __halves2half2(l2, l3);
}

// qm = question * w_mult -> fp16 hi/lo [b,q,e]
__global__ void make_qm(const float* __restrict__ question,
                        const float* __restrict__ wmv,
                        __half* __restrict__ hi, __half* __restrict__ lo) {
    size_t i = ((size_t)blockIdx.x * 256 + threadIdx.x) * 4;
    int e = (int)(i & (EE - 1));
    float4 q = *(const float4*)(question + i);
    float4 w = *(const float4*)(wmv + e);
    float v0 = q.x * w.x, v1 = q.y * w.y, v2 = q.z * w.z, v3 = q.w * w.w;
    __half h0, l0, h1, l1, h2, l2, h3, l3;
    split_h(v0, h0, l0); split_h(v1, h1, l1);
    split_h(v2, h2, l2); split_h(v3, h3, l3);
    *(__half2*)(hi + i)     = __halves2half2(h0, h1);
    *(__half2*)(hi + i + 2) = __halves2half2(h2, h3);
    *(__half2*)(lo + i)     = __halves2half2(l0, l1);
    *(__half2*)(lo + i + 2) = __halves2half2(l2, l3);
}

// merged row dots: rows [0, B*Q) -> qw = question . w_q ; rest -> cw = ctx . w_c
__global__ void dots_kernel(const float* __restrict__ question,
                            const float* __restrict__ context,
                            const float* __restrict__ w_q,
                            const float* __restrict__ w_c,
                            float* __restrict__ qw, float* __restrict__ cw) {
    int row  = blockIdx.x * 8 + (threadIdx.x >> 5);
    int lane = threadIdx.x & 31;
    const float* X;
    const float* w;
    float* out;
    if (row < BB * QQ) { X = question + (size_t)row * EE; w = w_q; out = qw + row; }
    else {
        int r2 = row - BB * QQ;
        X = context + (size_t)r2 * EE; w = w_c; out = cw + r2;
    }
    const float4* x  = (const float4*)X;
    const float4* wv = (const float4*)w;
    float s = 0.f;
    #pragma unroll
    for (int i = lane; i * 4 < EE; i += 32) {
        float4 a = x[i], b = wv[i];
        s += a.x * b.x + a.y * b.y + a.z * b.z + a.w * b.w;
    }
    s = warp_sum(s);
    if (lane == 0) *out = s;
}

// ------- softmax over q (Q=128): writes P fp16 hi/lo + rowmax ----------------
__global__ void softmax_q_kernel(const float* __restrict__ sim,
                                 __half* __restrict__ Phi, __half* __restrict__ Plo,
                                 float* __restrict__ rowmax) {
    int row  = blockIdx.x * 8 + (threadIdx.x >> 5);
    int lane = threadIdx.x & 31;
    const float4* p = (const float4*)(sim + (size_t)row * QQ);
    float4 v = p[lane];
    float m = fmaxf(fmaxf(v.x, v.y), fmaxf(v.z, v.w));
    m = warp_max(m);
    float ex = __expf(v.x - m), ey = __expf(v.y - m),
          ez = __expf(v.z - m), ew = __expf(v.w - m);
    float s = warp_sum(ex + ey + ez + ew);
    float inv = 1.f / s;
    float p0 = ex * inv, p1 = ey * inv, p2 = ez * inv, p3 = ew * inv;
    size_t o = (size_t)row * QQ + lane * 4;
    __half h0, l0, h1, l1, h2, l2, h3, l3;
    split_h(p0, h0, l0); split_h(p1, h1, l1);
    split_h(p2, h2, l2); split_h(p3, h3, l3);
    *(__half2*)(Phi + o)     = __halves2half2(h0, h1);
    *(__half2*)(Phi + o + 2) = __halves2half2(h2, h3);
    *(__half2*)(Plo + o)     = __halves2half2(l0, l1);
    *(__half2*)(Plo + o + 2) = __halves2half2(l2, l3);
    if (lane == 0) rowmax[row] = m;
}

// ---------------- softmax over c (C=1024) per batch --------------------------
__global__ void softmax_c_kernel(const float* __restrict__ rowmax,
                                 float* __restrict__ cwsoft) {
    int b   = blockIdx.x;
    int tid = threadIdx.x;
    int wid = tid >> 5, lane = tid & 31;
    __shared__ float redm[8], reds[8];
    float4 v = ((const float4*)(rowmax + b * CC))[tid];
    float m = fmaxf(fmaxf(v.x, v.y), fmaxf(v.z, v.w));
    m = warp_max(m);
    if (lane == 0) redm[wid] = m;
    __syncthreads();
    float bm = redm[0];
    #pragma unroll
    for (int i = 1; i < 8; i++) bm = fmaxf(bm, redm[i]);
    float ex = __expf(v.x - bm), ey = __expf(v.y - bm),
          ez = __expf(v.z - bm), ew = __expf(v.w - bm);
    float s = warp_sum(ex + ey + ez + ew);
    if (lane == 0) reds[wid] = s;
    __syncthreads();
    float bs = 0.f;
    #pragma unroll
    for (int i = 0; i < 8; i++) bs += reds[i];
    float inv = 1.f / bs;
    ((float4*)(cwsoft + b * CC))[tid] =
        make_float4(ex * inv, ey * inv, ez * inv, ew * inv);
}

// ------- q2c: partial over c-chunks then reduce ------------------------------
__global__ void q2c_part_kernel(const float* __restrict__ context,
                                const float* __restrict__ cwsoft,
                                float* __restrict__ part) {
    int b = blockIdx.y, ch = blockIdx.x, e = threadIdx.x;   // 512 threads
    const float* ctx = context + ((size_t)b * CC + ch * 128) * EE + e;
    const float* w   = cwsoft + b * CC + ch * 128;
    float s = 0.f;
    #pragma unroll 4
    for (int c = 0; c < 128; c++) s += w[c] * ctx[(size_t)c * EE];
    part[((size_t)b * 8 + ch) * EE + e] = s;
}
__global__ void q2c_reduce_kernel(const float* __restrict__ part,
                                  float* __restrict__ q2c) {
    int idx = blockIdx.x * 256 + threadIdx.x;   // B*E
    int b = idx / EE, e = idx % EE;
    float s = 0.f;
    #pragma unroll
    for (int ch = 0; ch < 8; ch++) s += part[((size_t)b * 8 + ch) * EE + e];
    q2c[idx] = s;
}

// ---------------- launch -----------------------------------------------------
extern "C" void kernel_launch(void* const* d_in, const int* in_sizes, int n_in,
                              void* d_out, int out_size) {
    const float* context  = (const float*)d_in[0];
    const float* question = (const float*)d_in[1];
    const float* mask     = (const float*)d_in[2];
    const float* w_q      = (const float*)d_in[3];
    const float* w_c      = (const float*)d_in[4];
    const float* w_m      = (const float*)d_in[5];
    const float* W1       = (const float*)d_in[6];
    const float* b1       = (const float*)d_in[7];
    const float* W2       = (const float*)d_in[8];
    const float* b2       = (const float*)d_in[9];
    float* out = (float*)d_out;

    float *qw, *cw, *sim, *rowmax, *cwsoft, *q2c, *q2cp;
    __half *ctx_hi, *ctx_lo, *qm_hi, *qm_lo, *qT_hi, *qT_lo, *P_hi, *P_lo;
    __half *att, *w1t_hi, *w1t_lo, *w2t_hi, *w2t_lo, *hbuf;
    cudaGetSymbolAddress((void**)&qw,     g_qw);
    cudaGetSymbolAddress((void**)&cw,     g_cw);
    cudaGetSymbolAddress((void**)&sim,    g_sim);
    cudaGetSymbolAddress((void**)&rowmax, g_rowmax);
    cudaGetSymbolAddress((void**)&cwsoft, g_cwsoft);
    cudaGetSymbolAddress((void**)&q2c,    g_q2c);
    cudaGetSymbolAddress((void**)&q2cp,   g_q2c_part);
    cudaGetSymbolAddress((void**)&ctx_hi, g_ctx_hi);
    cudaGetSymbolAddress((void**)&ctx_lo, g_ctx_lo);
    cudaGetSymbolAddress((void**)&qm_hi,  g_qm_hi);
    cudaGetSymbolAddress((void**)&qm_lo,  g_qm_lo);
    cudaGetSymbolAddress((void**)&qT_hi,  g_qT_hi);
    cudaGetSymbolAddress((void**)&qT_lo,  g_qT_lo);
    cudaGetSymbolAddress((void**)&P_hi,   g_P_hi);
    cudaGetSymbolAddress((void**)&P_lo,   g_P_lo);
    cudaGetSymbolAddress((void**)&att,    g_att);
    cudaGetSymbolAddress((void**)&w1t_hi, g_w1t_hi);
    cudaGetSymbolAddress((void**)&w1t_lo, g_w1t_lo);
    cudaGetSymbolAddress((void**)&w2t_hi, g_w2t_hi);
    cudaGetSymbolAddress((void**)&w2t_lo, g_w2t_lo);
    cudaGetSymbolAddress((void**)&hbuf,   g_h);

    const int SM3 = 2 * 4 * MATB;   // 81920: 3-term, 2-stage
    const int SM1 = 4 * 2 * MATB;   // 81920: 1-term, 4-stage
    cudaFuncSetAttribute(tgemm<0>, cudaFuncAttributeMaxDynamicSharedMemorySize, SM3);
    cudaFuncSetAttribute(tgemm<3>, cudaFuncAttributeMaxDynamicSharedMemorySize, SM3);
    cudaFuncSetAttribute(tgemm<1>, cudaFuncAttributeMaxDynamicSharedMemorySize, SM1);
    cudaFuncSetAttribute(tgemm<2>, cudaFuncAttributeMaxDynamicSharedMemorySize, SM1);

    // indices 0-2: prerequisites of tgemm<0>
    split4<<<(int)(((size_t)BB * CC * EE) / 1024), 256>>>(context, ctx_hi, ctx_lo);
    make_qm<<<(int)(((size_t)BB * QQ * EE) / 1024), 256>>>(question, w_m, qm_hi, qm_lo);
    dots_kernel<<<(BB * QQ + BB * CC) / 8, 256>>>(question, context, w_q, w_c, qw, cw);

    // index 3 (profiled): sim = ctx @ qm^T + cw[row] + qw[col]   (MODE 0)
    tgemm<0><<<dim3(1, CC / 128, BB), 256, SM3>>>(
        ctx_hi, ctx_lo, qm_hi, qm_lo, EE, (long)CC * EE, (long)QQ * EE,
        sim, nullptr, cw, qw);

    make_qT<<<dim3(QQ / 32, EE / 32, BB), dim3(32, 8)>>>(question, qT_hi, qT_lo);
    transW<<<dim3(FE / 32, HH / 32), dim3(32, 8)>>>(W1, w1t_hi, w1t_lo, FE, HH);
    transW<<<dim3(HH / 32, FE / 32), dim3(32, 8)>>>(W2, w2t_hi, w2t_lo, HH, FE);

    softmax_q_kernel<<<BB * CC / 8, 256>>>(sim, P_hi, P_lo, rowmax);
    softmax_c_kernel<<<BB, 256>>>(rowmax, cwsoft);
    q2c_part_kernel<<<dim3(8, BB), 512>>>(context, cwsoft, q2cp);
    q2c_reduce_kernel<<<BB * EE / 256, 256>>>(q2cp, q2c);

    // c2q = P @ question, epilogue builds attended fp16  (MODE 3)
    tgemm<3><<<dim3(EE / 128, CC / 128, BB), 256, SM3>>>(
        P_hi, P_lo, qT_hi, qT_lo, QQ, (long)CC * QQ, (long)EE * QQ,
        nullptr, att, context, q2c);

    // h = (att @ W1 + b1) * mask   (MODE 1, 1-term fp16)
    tgemm<1><<<dim3(HH / 128, (BB * CC) / 128, 1), 256, SM1>>>(
        att, nullptr, w1t_hi, w1t_lo, FE, 0, 0,
        nullptr, hbuf, b1, mask);

    // out = relu((h @ W2 + b2) * mask)   (MODE 2, 1-term fp16)
    tgemm<2><<<dim3(FE / 128, (BB * CC) / 128, 1), 256, SM1>>>(
        hbuf, nullptr, w2t_hi, w2t_lo, HH, 0, 0,
        out, nullptr, b2, mask);
}

// round 12
// speedup vs baseline: 7.6071x; 1.0146x over previous
#include <cuda_runtime.h>
#include <cuda_fp16.h>
#include <math.h>
#include <stdint.h>

#define BB 8
#define CC 1024
#define QQ 128
#define EE 512
#define HH 1024
#define FE 2048  /* 4*E */

// ------- scratch (static device globals; 256B-aligned) -----------------------
__device__ __align__(256) float g_qw[BB * QQ];
__device__ __align__(256) float g_cw[BB * CC];
__device__ __align__(256) float g_sim[BB * CC * QQ];
__device__ __align__(256) float g_rowmax[BB * CC];
__device__ __align__(256) float g_cwsoft[BB * CC];
__device__ __align__(256) float g_q2c[BB * EE];
__device__ __align__(256) float g_q2c_part[BB * 8 * EE];

__device__ __align__(256) __half g_ctx_hi[(size_t)BB * CC * EE];
__device__ __align__(256) __half g_ctx_lo[(size_t)BB * CC * EE];
__device__ __align__(256) __half g_qm_hi[(size_t)BB * QQ * EE];
__device__ __align__(256) __half g_qm_lo[(size_t)BB * QQ * EE];
__device__ __align__(256) __half g_qT[(size_t)BB * EE * QQ];     // single fp16
__device__ __align__(256) __half g_P[(size_t)BB * CC * QQ];      // single fp16

__device__ __align__(256) __half g_att[(size_t)BB * CC * FE];    // single fp16
__device__ __align__(256) __half g_w1t[(size_t)HH * FE];         // [N=HH, K=FE]
__device__ __align__(256) __half g_w2t[(size_t)FE * HH];         // [N=FE, K=HH]
__device__ __align__(256) __half g_h[(size_t)BB * CC * HH];      // single fp16

// ---------------- small helpers ---------------------------------------------
__device__ __forceinline__ float warp_sum(float v) {
    #pragma unroll
    for (int o = 16; o > 0; o >>= 1) v += __shfl_xor_sync(0xFFFFFFFFu, v, o);
    return v;
}
__device__ __forceinline__ float warp_max(float v) {
    #pragma unroll
    for (int o = 16; o > 0; o >>= 1) v = fmaxf(v, __shfl_xor_sync(0xFFFFFFFFu, v, o));
    return v;
}
__device__ __forceinline__ uint32_t s2u(const void* p) {
    uint32_t a;
    asm("{ .reg .u64 t; cvta.to.shared.u64 t, %1; cvt.u32.u64 %0, t; }"
        : "=r"(a) : "l"(p));
    return a;
}
__device__ __forceinline__ void cpa16(uint32_t d, const void* s) {
    asm volatile("cp.async.cg.shared.global [%0], [%1], 16;" :: "r"(d), "l"(s));
}
#define CP_COMMIT() asm volatile("cp.async.commit_group;" ::: "memory")
#define CP_WAIT(N)  asm volatile("cp.async.wait_group %0;" :: "n"(N) : "memory")

__device__ __forceinline__ void ldsm4(uint32_t* r, uint32_t addr) {
    asm volatile("ldmatrix.sync.aligned.m8n8.x4.shared.b16 {%0,%1,%2,%3}, [%4];"
                 : "=r"(r[0]), "=r"(r[1]), "=r"(r[2]), "=r"(r[3]) : "r"(addr));
}
__device__ __forceinline__ void mma16816(float* c, const uint32_t* a,
                                         const uint32_t* b) {
    asm volatile(
        "mma.sync.aligned.m16n8k16.row.col.f32.f16.f16.f32 "
        "{%0,%1,%2,%3}, {%4,%5,%6,%7}, {%8,%9}, {%0,%1,%2,%3};"
        : "+f"(c[0]), "+f"(c[1]), "+f"(c[2]), "+f"(c[3])
        : "r"(a[0]), "r"(a[1]), "r"(a[2]), "r"(a[3]), "r"(b[0]), "r"(b[1]));
}
__device__ __forceinline__ void split_h(float v, __half& h, __half& l) {
    h = __float2half_rn(v);
    l = __float2half_rn(v - __half2float(h));
}

// ========================= mma.sync fp16 GEMM ================================
// Tile 128x128, K-chunk 32, fp32 accumulate.
// MODE 0 (3-term): sim = (Ahi+Alo)@(Bhi+Blo)^T + cw[row] + qw[col], 2-stage.
// MODES 1,2,3 (1-term): C = A @ B^T pure fp16, 4-stage pipe, B-frag prefetch.
// MODE 1: h   = (acc + bias[col]) * mask[row]              -> fp16
// MODE 2: out = relu((acc + bias[col]) * mask[row])        -> fp32
// MODE 3: c2q epilogue -> attended[4 segs] fp16 using ctx,q2c
#define TS 80            /* smem row stride bytes (32 fp16 + pad) */
#define MATB (128 * TS)  /* 10240 bytes per matrix tile */

template <int MODE>
__global__ void __launch_bounds__(256) tgemm(
    const __half* __restrict__ Ahi, const __half* __restrict__ Alo,
    const __half* __restrict__ Bhi, const __half* __restrict__ Blo,
    int K, long sA, long sB,
    float* __restrict__ Cfp, __half* __restrict__ Oh,
    const float* __restrict__ x0, const float* __restrict__ x1) {
    constexpr int TERMS = (MODE == 0) ? 3 : 1;
    constexpr int NMAT  = (TERMS == 3) ? 4 : 2;
    constexpr int STGB  = NMAT * MATB;
    constexpr int BHI_OFF = (TERMS == 3) ? 2 * MATB : MATB;

    extern __shared__ char sm[];
    uint32_t sb = s2u(sm);
    int tid = threadIdx.x, wid = tid >> 5, lane = tid & 31;
    int z = blockIdx.z;
    int rowBase = blockIdx.y * 128, colBase = blockIdx.x * 128;
    int wm = wid & 3, wn = wid >> 2;

    const char* pAhi = (const char*)(Ahi + (size_t)z * sA);
    const char* pAlo = (TERMS == 3) ? (const char*)(Alo + (size_t)z * sA) : nullptr;
    const char* pBhi = (const char*)(Bhi + (size_t)z * sB);
    const char* pBlo = (TERMS == 3) ? (const char*)(Blo + (size_t)z * sB) : nullptr;
    long Kb = (long)K * 2;

    uint32_t aBaseOff = (uint32_t)(wm * 32 + (lane & 15)) * TS + ((lane >> 4) << 4);
    uint32_t bBaseOff = BHI_OFF +
        (uint32_t)(wn * 64 + (lane & 7) + ((lane >> 4) << 3)) * TS +
        (((lane >> 3) & 1) << 4);

    float acc[2][8][4];
    #pragma unroll
    for (int i = 0; i < 2; i++)
        #pragma unroll
        for (int j = 0; j < 8; j++)
            #pragma unroll
            for (int k = 0; k < 4; k++) acc[i][j][k] = 0.f;

    auto load_stage = [&](int st, int kc) {
        uint32_t base = sb + st * STGB;
        long koff = (long)kc * 64;
        #pragma unroll
        for (int i = 0; i < 2; i++) {
            int c = tid + (i << 8);
            int r = c >> 2, f = c & 3;
            uint32_t doff = (uint32_t)r * TS + (f << 4);
            long aoff = (long)(rowBase + r) * Kb + koff + (f << 4);
            long boff = (long)(colBase + r) * Kb + koff + (f << 4);
            cpa16(base + doff, pAhi + aoff);
            if (TERMS == 3) cpa16(base + MATB + doff, pAlo + aoff);
            cpa16(base + BHI_OFF + doff, pBhi + boff);
            if (TERMS == 3) cpa16(base + BHI_OFF + MATB + doff, pBlo + boff);
        }
    };

    auto compute_stage = [&](int st) {
        uint32_t abase = sb + st * STGB + aBaseOff;
        uint32_t bbase = sb + st * STGB + bBaseOff;
        #pragma unroll
        for (int ks = 0; ks < 2; ks++) {
            uint32_t ah[2][4], al[2][4];
            #pragma unroll
            for (int mi = 0; mi < 2; mi++) {
                uint32_t aa = abase + mi * (16 * TS) + ks * 32;
                ldsm4(ah[mi], aa);
                if (TERMS == 3) ldsm4(al[mi], aa + MATB);
            }
            if (TERMS == 1) {
                // B-fragment double-buffer: prefetch t4+1 while issuing MMAs of t4
                uint32_t bb[2][4];
                ldsm4(bb[0], bbase + ks * 32);
                #pragma unroll
                for (int t4 = 0; t4 < 4; t4++) {
                    int cur = t4 & 1;
                    if (t4 < 3)
                        ldsm4(bb[cur ^ 1], bbase + (t4 + 1) * (16 * TS) + ks * 32);
                    #pragma unroll
                    for (int mi = 0; mi < 2; mi++)
                        #pragma unroll
                        for (int h = 0; h < 2; h++)
                            mma16816(acc[mi][t4 * 2 + h], ah[mi], bb[cur] + 2 * h);
                }
            } else {
                #pragma unroll
                for (int t4 = 0; t4 < 4; t4++) {
                    uint32_t bh[4], bl[4];
                    uint32_t ba = bbase + t4 * (16 * TS) + ks * 32;
                    ldsm4(bh, ba);
                    ldsm4(bl, ba + MATB);
                    #pragma unroll
                    for (int mi = 0; mi < 2; mi++)
                        #pragma unroll
                        for (int h = 0; h < 2; h++) {
                            float* c = acc[mi][t4 * 2 + h];
                            mma16816(c, ah[mi], bh + 2 * h);
                            mma16816(c, ah[mi], bl + 2 * h);
                            mma16816(c, al[mi], bh + 2 * h);
                        }
                }
            }
        }
    };

    int nch = K >> 5;
    if (TERMS == 3) {
        // 2-stage, two syncs per chunk (proven R8 structure)
        load_stage(0, 0);
        CP_COMMIT();
        for (int kc = 0; kc < nch; kc++) {
            int st = kc & 1;
            if (kc + 1 < nch) {
                load_stage(st ^ 1, kc + 1);
                CP_COMMIT();
                CP_WAIT(1);
            } else {
                CP_WAIT(0);
            }
            __syncthreads();
            compute_stage(st);
            __syncthreads();
        }
    } else {
        // 4-stage, one sync per chunk (nch >= 4 for all 1-term uses)
        load_stage(0, 0); CP_COMMIT();
        load_stage(1, 1); CP_COMMIT();
        load_stage(2, 2); CP_COMMIT();
        for (int kc = 0; kc < nch; kc++) {
            if (kc + 2 < nch)      { CP_WAIT(2); }
            else if (kc + 1 < nch) { CP_WAIT(1); }
            else                   { CP_WAIT(0); }
            __syncthreads();
            if (kc + 3 < nch) { load_stage((kc + 3) & 3, kc + 3); CP_COMMIT(); }
            compute_stage(kc & 3);
        }
    }

    #pragma unroll
    for (int mi = 0; mi < 2; mi++) {
        int r0 = rowBase + wm * 32 + mi * 16 + (lane >> 2);
        int r1 = r0 + 8;
        float mk0 = 0.f, mk1 = 0.f;
        if (MODE == 1 || MODE == 2) { mk0 = x1[r0]; mk1 = x1[r1]; }
        if (MODE == 0) { mk0 = x0[z * CC + r0]; mk1 = x0[z * CC + r1]; }
        #pragma unroll
        for (int ni = 0; ni < 8; ni++) {
            int col = colBase + wn * 64 + ni * 8 + (lane & 3) * 2;
            float a0 = acc[mi][ni][0], a1 = acc[mi][ni][1];
            float a2 = acc[mi][ni][2], a3 = acc[mi][ni][3];
            if (MODE == 0) {
                float q0 = x1[z * QQ + col], q1 = x1[z * QQ + col + 1];
                float* C = Cfp + ((size_t)z * CC) * QQ;
                *(float2*)(C + (size_t)r0 * QQ + col) =
                    make_float2(a0 + mk0 + q0, a1 + mk0 + q1);
                *(float2*)(C + (size_t)r1 * QQ + col) =
                    make_float2(a2 + mk1 + q0, a3 + mk1 + q1);
            } else if (MODE == 3) {
                const float* ctx = x0 + (size_t)z * CC * EE;
                const float* q2b = x1 + (size_t)z * EE;
                float2 ca = *(const float2*)(ctx + (size_t)r0 * EE + col);
                float2 cb = *(const float2*)(ctx + (size_t)r1 * EE + col);
                float2 qv = *(const float2*)(q2b + col);
                size_t o0 = ((size_t)z * CC + r0) * FE + col;
                size_t o1 = ((size_t)z * CC + r1) * FE + col;
                auto sth = [&](size_t off, float a, float b) {
                    *(__half2*)(Oh + off) =
                        __halves2half2(__float2half_rn(a), __float2half_rn(b));
                };
                sth(o0,          ca.x,        ca.y);
                sth(o0 + EE,     a0,          a1);
                sth(o0 + 2 * EE, ca.x * a0,   ca.y * a1);
                sth(o0 + 3 * EE, ca.x * qv.x, ca.y * qv.y);
                sth(o1,          cb.x,        cb.y);
                sth(o1 + EE,     a2,          a3);
                sth(o1 + 2 * EE, cb.x * a2,   cb.y * a3);
                sth(o1 + 3 * EE, cb.x * qv.x, cb.y * qv.y);
            } else {
                float bv0 = x0[col], bv1 = x0[col + 1];
                float v0 = (a0 + bv0) * mk0;
                float v1 = (a1 + bv1) * mk0;
                float v2 = (a2 + bv0) * mk1;
                float v3 = (a3 + bv1) * mk1;
                if (MODE == 2) {
                    size_t o0 = (size_t)r0 * FE + col;
                    size_t o1 = (size_t)r1 * FE + col;
                    *(float2*)(Cfp + o0) = make_float2(fmaxf(v0, 0.f), fmaxf(v1, 0.f));
                    *(float2*)(Cfp + o1) = make_float2(fmaxf(v2, 0.f), fmaxf(v3, 0.f));
                } else {
                    size_t o0 = (size_t)r0 * HH + col;
                    size_t o1 = (size_t)r1 * HH + col;
                    *(__half2*)(Oh + o0) =
                        __halves2half2(__float2half_rn(v0), __float2half_rn(v1));
                    *(__half2*)(Oh + o1) =
                        __halves2half2(__float2half_rn(v2), __float2half_rn(v3));
                }
            }
        }
    }
}

// ---------------- W transpose -> single fp16 ---------------------------------
__global__ void transW(const float* __restrict__ W, __half* __restrict__ T,
                       int K, int N) {
    __shared__ float t[32][33];
    int k0 = blockIdx.x * 32, n0 = blockIdx.y * 32;
    int tx = threadIdx.x, ty = threadIdx.y;   // 32 x 8
    #pragma unroll
    for (int i = 0; i < 4; i++)
        t[ty + i * 8][tx] = W[(size_t)(k0 + ty + i * 8) * N + n0 + tx];
    __syncthreads();
    #pragma unroll
    for (int i = 0; i < 4; i++) {
        float v = t[tx][ty + i * 8];
        int n = n0 + ty + i * 8, k = k0 + tx;
        T[(size_t)n * K + k] = __float2half_rn(v);
    }
}

// question^T -> qT single fp16 [b,e,q]
__global__ void make_qT(const float* __restrict__ question,
                        __half* __restrict__ T) {
    __shared__ float t[32][33];
    int b = blockIdx.z;
    int q0 = blockIdx.x * 32, e0 = blockIdx.y * 32;
    int tx = threadIdx.x, ty = threadIdx.y;
    #pragma unroll
    for (int i = 0; i < 4; i++)
        t[ty + i * 8][tx] = question[((size_t)b * QQ + q0 + ty + i * 8) * EE + e0 + tx];
    __syncthreads();
    #pragma unroll
    for (int i = 0; i < 4; i++) {
        float v = t[tx][ty + i * 8];
        size_t o = ((size_t)b * EE + e0 + ty + i * 8) * QQ + q0 + tx;
        T[o] = __float2half_rn(v);
    }
}

// elementwise fp32 -> fp16 hi/lo (4 per thread)
__global__ void split4(const float* __restrict__ src, __half* __restrict__ hi,
                       __half* __restrict__ lo) {
    size_t i = ((size_t)blockIdx.x * 256 + threadIdx.x) * 4;
    float4 v = *(const float4*)(src + i);
    __half h0, l0, h1, l1, h2, l2, h3, l3;
    split_h(v.x, h0, l0); split_h(v.y, h1, l1);
    split_h(v.z, h2, l2); split_h(v.w, h3, l3);
    *(__half2*)(hi + i)     = __halves2half2(h0, h1);
    *(__half2*)(hi + i + 2) = __halves2half2(h2, h3);
    *(__half2*)(lo + i)     = __halves2half2(l0, l1);
    *(__half2*)(lo + i + 2) = __halves2half2(l2, l3);
}

// qm = question * w_mult -> fp16 hi/lo [b,q,e]
__global__ void make_qm(const float* __restrict__ question,
                        const float* __restrict__ wmv,
                        __half* __restrict__ hi, __half* __restrict__ lo) {
    size_t i = ((size_t)blockIdx.x * 256 + threadIdx.x) * 4;
    int e = (int)(i & (EE - 1));
    float4 q = *(const float4*)(question + i);
    float4 w = *(const float4*)(wmv + e);
    float v0 = q.x * w.x, v1 = q.y * w.y, v2 = q.z * w.z, v3 = q.w * w.w;
    __half h0, l0, h1, l1, h2, l2, h3, l3;
    split_h(v0, h0, l0); split_h(v1, h1, l1);
    split_h(v2, h2, l2); split_h(v3, h3, l3);
    *(__half2*)(hi + i)     = __halves2half2(h0, h1);
    *(__half2*)(hi + i + 2) = __halves2half2(h2, h3);
    *(__half2*)(lo + i)     = __halves2half2(l0, l1);
    *(__half2*)(lo + i + 2) = __halves2half2(l2, l3);
}

// merged row dots: rows [0, B*Q) -> qw = question . w_q ; rest -> cw = ctx . w_c
__global__ void dots_kernel(const float* __restrict__ question,
                            const float* __restrict__ context,
                            const float* __restrict__ w_q,
                            const float* __restrict__ w_c,
                            float* __restrict__ qw, float* __restrict__ cw) {
    int row  = blockIdx.x * 8 + (threadIdx.x >> 5);
    int lane = threadIdx.x & 31;
    const float* X;
    const float* w;
    float* out;
    if (row < BB * QQ) { X = question + (size_t)row * EE; w = w_q; out = qw + row; }
    else {
        int r2 = row - BB * QQ;
        X = context + (size_t)r2 * EE; w = w_c; out = cw + r2;
    }
    const float4* x  = (const float4*)X;
    const float4* wv = (const float4*)w;
    float s = 0.f;
    #pragma unroll
    for (int i = lane; i * 4 < EE; i += 32) {
        float4 a = x[i], b = wv[i];
        s += a.x * b.x + a.y * b.y + a.z * b.z + a.w * b.w;
    }
    s = warp_sum(s);
    if (lane == 0) *out = s;
}

// ------- softmax over q (Q=128): writes P single fp16 + rowmax ---------------
__global__ void softmax_q_kernel(const float* __restrict__ sim,
                                 __half* __restrict__ P,
                                 float* __restrict__ rowmax) {
    int row  = blockIdx.x * 8 + (threadIdx.x >> 5);
    int lane = threadIdx.x & 31;
    const float4* p = (const float4*)(sim + (size_t)row * QQ);
    float4 v = p[lane];
    float m = fmaxf(fmaxf(v.x, v.y), fmaxf(v.z, v.w));
    m = warp_max(m);
    float ex = __expf(v.x - m), ey = __expf(v.y - m),
          ez = __expf(v.z - m), ew = __expf(v.w - m);
    float s = warp_sum(ex + ey + ez + ew);
    float inv = 1.f / s;
    size_t o = (size_t)row * QQ + lane * 4;
    *(__half2*)(P + o) =
        __halves2half2(__float2half_rn(ex * inv), __float2half_rn(ey * inv));
    *(__half2*)(P + o + 2) =
        __halves2half2(__float2half_rn(ez * inv), __float2half_rn(ew * inv));
    if (lane == 0) rowmax[row] = m;
}

// ---------------- softmax over c (C=1024) per batch --------------------------
__global__ void softmax_c_kernel(const float* __restrict__ rowmax,
                                 float* __restrict__ cwsoft) {
    int b   = blockIdx.x;
    int tid = threadIdx.x;
    int wid = tid >> 5, lane = tid & 31;
    __shared__ float redm[8], reds[8];
    float4 v = ((const float4*)(rowmax + b * CC))[tid];
    float m = fmaxf(fmaxf(v.x, v.y), fmaxf(v.z, v.w));
    m = warp_max(m);
    if (lane == 0) redm[wid] = m;
    __syncthreads();
    float bm = redm[0];
    #pragma unroll
    for (int i = 1; i < 8; i++) bm = fmaxf(bm, redm[i]);
    float ex = __expf(v.x - bm), ey = __expf(v.y - bm),
          ez = __expf(v.z - bm), ew = __expf(v.w - bm);
    float s = warp_sum(ex + ey + ez + ew);
    if (lane == 0) reds[wid] = s;
    __syncthreads();
    float bs = 0.f;
    #pragma unroll
    for (int i = 0; i < 8; i++) bs += reds[i];
    float inv = 1.f / bs;
    ((float4*)(cwsoft + b * CC))[tid] =
        make_float4(ex * inv, ey * inv, ez * inv, ew * inv);
}

// ------- q2c: partial over c-chunks then reduce ------------------------------
__global__ void q2c_part_kernel(const float* __restrict__ context,
                                const float* __restrict__ cwsoft,
                                float* __restrict__ part) {
    int b = blockIdx.y, ch = blockIdx.x, e = threadIdx.x;   // 512 threads
    const float* ctx = context + ((size_t)b * CC + ch * 128) * EE + e;
    const float* w   = cwsoft + b * CC + ch * 128;
    float s = 0.f;
    #pragma unroll 4
    for (int c = 0; c < 128; c++) s += w[c] * ctx[(size_t)c * EE];
    part[((size_t)b * 8 + ch) * EE + e] = s;
}
__global__ void q2c_reduce_kernel(const float* __restrict__ part,
                                  float* __restrict__ q2c) {
    int idx = blockIdx.x * 256 + threadIdx.x;   // B*E
    int b = idx / EE, e = idx % EE;
    float s = 0.f;
    #pragma unroll
    for (int ch = 0; ch < 8; ch++) s += part[((size_t)b * 8 + ch) * EE + e];
    q2c[idx] = s;
}

// ---------------- launch -----------------------------------------------------
extern "C" void kernel_launch(void* const* d_in, const int* in_sizes, int n_in,
                              void* d_out, int out_size) {
    const float* context  = (const float*)d_in[0];
    const float* question = (const float*)d_in[1];
    const float* mask     = (const float*)d_in[2];
    const float* w_q      = (const float*)d_in[3];
    const float* w_c      = (const float*)d_in[4];
    const float* w_m      = (const float*)d_in[5];
    const float* W1       = (const float*)d_in[6];
    const float* b1       = (const float*)d_in[7];
    const float* W2       = (const float*)d_in[8];
    const float* b2       = (const float*)d_in[9];
    float* out = (float*)d_out;

    float *qw, *cw, *sim, *rowmax, *cwsoft, *q2c, *q2cp;
    __half *ctx_hi, *ctx_lo, *qm_hi, *qm_lo, *qT, *P;
    __half *att, *w1t, *w2t, *hbuf;
    cudaGetSymbolAddress((void**)&qw,     g_qw);
    cudaGetSymbolAddress((void**)&cw,     g_cw);
    cudaGetSymbolAddress((void**)&sim,    g_sim);
    cudaGetSymbolAddress((void**)&rowmax, g_rowmax);
    cudaGetSymbolAddress((void**)&cwsoft, g_cwsoft);
    cudaGetSymbolAddress((void**)&q2c,    g_q2c);
    cudaGetSymbolAddress((void**)&q2cp,   g_q2c_part);
    cudaGetSymbolAddress((void**)&ctx_hi, g_ctx_hi);
    cudaGetSymbolAddress((void**)&ctx_lo, g_ctx_lo);
    cudaGetSymbolAddress((void**)&qm_hi,  g_qm_hi);
    cudaGetSymbolAddress((void**)&qm_lo,  g_qm_lo);
    cudaGetSymbolAddress((void**)&qT,     g_qT);
    cudaGetSymbolAddress((void**)&P,      g_P);
    cudaGetSymbolAddress((void**)&att,    g_att);
    cudaGetSymbolAddress((void**)&w1t,    g_w1t);
    cudaGetSymbolAddress((void**)&w2t,    g_w2t);
    cudaGetSymbolAddress((void**)&hbuf,   g_h);

    const int SM3 = 2 * 4 * MATB;   // 81920: 3-term, 2-stage
    const int SM1 = 4 * 2 * MATB;   // 81920: 1-term, 4-stage
    cudaFuncSetAttribute(tgemm<0>, cudaFuncAttributeMaxDynamicSharedMemorySize, SM3);
    cudaFuncSetAttribute(tgemm<1>, cudaFuncAttributeMaxDynamicSharedMemorySize, SM1);
    cudaFuncSetAttribute(tgemm<2>, cudaFuncAttributeMaxDynamicSharedMemorySize, SM1);
    cudaFuncSetAttribute(tgemm<3>, cudaFuncAttributeMaxDynamicSharedMemorySize, SM1);

    // indices 0-2: prerequisites of tgemm<0>
    split4<<<(int)(((size_t)BB * CC * EE) / 1024), 256>>>(context, ctx_hi, ctx_lo);
    make_qm<<<(int)(((size_t)BB * QQ * EE) / 1024), 256>>>(question, w_m, qm_hi, qm_lo);
    dots_kernel<<<(BB * QQ + BB * CC) / 8, 256>>>(question, context, w_q, w_c, qw, cw);

    // index 3 (profiled): sim = ctx @ qm^T + cw[row] + qw[col]   (MODE 0)
    tgemm<0><<<dim3(1, CC / 128, BB), 256, SM3>>>(
        ctx_hi, ctx_lo, qm_hi, qm_lo, EE, (long)CC * EE, (long)QQ * EE,
        sim, nullptr, cw, qw);

    make_qT<<<dim3(QQ / 32, EE / 32, BB), dim3(32, 8)>>>(question, qT);
    transW<<<dim3(FE / 32, HH / 32), dim3(32, 8)>>>(W1, w1t, FE, HH);
    transW<<<dim3(HH / 32, FE / 32), dim3(32, 8)>>>(W2, w2t, HH, FE);

    softmax_q_kernel<<<BB * CC / 8, 256>>>(sim, P, rowmax);
    softmax_c_kernel<<<BB, 256>>>(rowmax, cwsoft);
    q2c_part_kernel<<<dim3(8, BB), 512>>>(context, cwsoft, q2cp);
    q2c_reduce_kernel<<<BB * EE / 256, 256>>>(q2cp, q2c);

    // c2q = P @ question (1-term), epilogue builds attended fp16  (MODE 3)
    tgemm<3><<<dim3(EE / 128, CC / 128, BB), 256, SM1>>>(
        P, nullptr, qT, nullptr, QQ, (long)CC * QQ, (long)EE * QQ,
        nullptr, att, context, q2c);

    // h = (att @ W1 + b1) * mask   (MODE 1, 1-term fp16)
    tgemm<1><<<dim3(HH / 128, (BB * CC) / 128, 1), 256, SM1>>>(
        att, nullptr, w1t, nullptr, FE, 0, 0,
        nullptr, hbuf, b1, mask);

    // out = relu((h @ W2 + b2) * mask)   (MODE 2, 1-term fp16)
    tgemm<2><<<dim3(FE / 128, (BB * CC) / 128, 1), 256, SM1>>>(
        hbuf, nullptr, w2t, nullptr, HH, 0, 0,
        out, nullptr, b2, mask);
}